// round 7
// baseline (speedup 1.0000x reference)
#include <cuda_runtime.h>
#include <cuda_bf16.h>
#include <math.h>

// ---------------------------------------------------------------------------
// GNNModel: hyperbolic GNN message passing (c = 1e-6)
// ---------------------------------------------------------------------------

#define MAX_NODE 100000
#define MAX_VOCAB 512
#define MAX_B 256
#define DD 64
#define TILES 4
#define ROWS_PER_TILE 32
#define ROWS_PER_BLOCK (TILES * ROWS_PER_TILE)   // 128

// attention tables in bf16 (only feed sigmoid(relu(.)@Wattn) — error << 1e-3)
__device__ __align__(16) __nv_bfloat16 g_hs_projh [MAX_NODE * DD];
__device__ __align__(16) __nv_bfloat16 g_rel_projh[MAX_VOCAB * DD];
__device__ __align__(16) __nv_bfloat16 g_qr_projh [MAX_B * DD];
__device__ float2 g_hs_sc [MAX_NODE];        // (fac*ps, ||expmap0||^2 clamped)
__device__ float  g_hr_h  [MAX_VOCAB * DD];  // expmap0(rela_embed[r]) projected
__device__ float  g_hr_y2 [MAX_VOCAB];       // ||hr_h||^2

#define SC 1.0e-3f                    // sqrt(c), c = 1e-6
#define CC 1.0e-6f
#define MAXNORM (0.996f / SC)
#define MN2 (MAXNORM * MAXNORM)

// ---- packed f32x2 helpers ----
__device__ __forceinline__ unsigned long long pack2(float a, float b) {
    unsigned long long r;
    asm("mov.b64 %0, {%1, %2};" : "=l"(r)
        : "r"(__float_as_uint(a)), "r"(__float_as_uint(b)));
    return r;
}
__device__ __forceinline__ void unpack2(unsigned long long v, float& a, float& b) {
    unsigned lo, hi;
    asm("mov.b64 {%0, %1}, %2;" : "=r"(lo), "=r"(hi) : "l"(v));
    a = __uint_as_float(lo); b = __uint_as_float(hi);
}
__device__ __forceinline__ unsigned long long fma2(
    unsigned long long a, unsigned long long b, unsigned long long c) {
    unsigned long long d;
    asm("fma.rn.f32x2 %0, %1, %2, %3;" : "=l"(d) : "l"(a), "l"(b), "l"(c));
    return d;
}
// bf16 pair (packed in u32) -> two f32, pure ALU
__device__ __forceinline__ float bflo(unsigned u) { return __uint_as_float(u << 16); }
__device__ __forceinline__ float bfhi(unsigned u) { return __uint_as_float(u & 0xffff0000u); }

// artanh(z)/z as poly in z^2 (valid z^2 < 0.09, guarded fallback above)
__device__ __forceinline__ float artanh_ratio(float z2) {
    float f = fmaf(z2, fmaf(z2, fmaf(z2, fmaf(z2, 1.0f/9.0f, 1.0f/7.0f),
                                     0.2f), 1.0f/3.0f), 1.0f);
    if (z2 > 0.09f) {
        float z = sqrtf(z2);
        float zc = fminf(z, 1.0f - 1e-5f);
        f = 0.5f * (log1pf(zc) - log1pf(-zc)) / z;
    }
    return f;
}
// tanh(z)/z as poly in z^2 (valid z^2 < 0.09, guarded)
__device__ __forceinline__ float tanh_ratio(float z2) {
    float f = fmaf(z2, fmaf(z2, fmaf(z2, -17.0f/315.0f, 2.0f/15.0f),
                            -1.0f/3.0f), 1.0f);
    if (z2 > 0.09f) {
        float z = sqrtf(z2);
        f = tanhf(fminf(z, 15.0f)) / z;
    }
    return f;
}

// ---------------------------------------------------------------------------
// fused prep: one launch; blockIdx routes to mode. 128 rows per block,
// 32 rows per tile, 8 rows per 64-thread group. Norms computed at staging
// (shuffles under the staging barrier), not in the matvec loop.
// ---------------------------------------------------------------------------
__global__ __launch_bounds__(256) void prep_all(
    const float* __restrict__ Ws, const float* __restrict__ Wr,
    const float* __restrict__ Wqr, const float* __restrict__ hidden,
    const float* __restrict__ rela, const int* __restrict__ q_rel,
    const float* __restrict__ Wqr_b, float* __restrict__ zout,
    int n_node, int n_vocab, int nB, int nb0, int nb1)
{
    __shared__ float Wst[DD][DD + 1];                 // Wst[k][j] = W[j*64+k]
    __shared__ __align__(16) float hT[4][DD * 8];     // hT[g][k*8 + r]
    __shared__ float nrm[4][2][8];

    int mode, bidx, n_rows;
    const float* W; const float* src;
    if ((int)blockIdx.x < nb0) {
        mode = 0; bidx = blockIdx.x; W = Ws; src = hidden; n_rows = n_node;
    } else if ((int)blockIdx.x < nb0 + nb1) {
        mode = 1; bidx = blockIdx.x - nb0; W = Wr; src = rela; n_rows = n_vocab;
    } else {
        mode = 2; bidx = blockIdx.x - nb0 - nb1; W = Wqr; src = rela; n_rows = nB;
    }

    int t = threadIdx.x;
    for (int i = t; i < DD * DD; i += 256) Wst[i & 63][i >> 6] = W[i];

    __nv_bfloat16* projh = (mode == 0) ? g_hs_projh :
                           (mode == 1) ? g_rel_projh : g_qr_projh;

    int gq = t >> 6, j = t & 63, half = (t >> 5) & 1, lane = t & 31;
    float bias = (mode == 2) ? Wqr_b[j] : 0.0f;

    float pf[8];
    // prefetch tile 0: thread owns column j of rows base+8*gq+u
    {
        int rbase = bidx * ROWS_PER_BLOCK + gq * 8;
#pragma unroll
        for (int u = 0; u < 8; u++) {
            int row = rbase + u;
            float v = 0.0f;
            if (row < n_rows) {
                int sr = (mode == 2) ? __ldg(&q_rel[row]) : row;
                v = __ldg(&src[sr * DD + j]);
            }
            pf[u] = v;
        }
    }

    for (int tile = 0; tile < TILES; tile++) {
        int base = bidx * ROWS_PER_BLOCK + tile * ROWS_PER_TILE;
        if (base >= n_rows) break;

        if (tile > 0) __syncthreads();     // hT free from previous compute
        // stage: two STS.128, conflict-free (consecutive words per thread)
        *(float4*)&hT[gq][j * 8]     = make_float4(pf[0], pf[1], pf[2], pf[3]);
        *(float4*)&hT[gq][j * 8 + 4] = make_float4(pf[4], pf[5], pf[6], pf[7]);

        // per-row norms via shuffle (covered by the staging barrier)
        if (mode != 2) {
            float nv[8];
#pragma unroll
            for (int u = 0; u < 8; u++) nv[u] = pf[u] * pf[u];
#pragma unroll
            for (int o = 16; o; o >>= 1) {
#pragma unroll
                for (int u = 0; u < 8; u++)
                    nv[u] += __shfl_xor_sync(0xffffffffu, nv[u], o);
            }
            if (lane == 0) {
#pragma unroll
                for (int u = 0; u < 8; u++) nrm[gq][half][u] = nv[u];
            }
        }
        __syncthreads();

        // prefetch next tile (LDG latency hidden under compute)
        int nbase = base + ROWS_PER_TILE;
        if (tile + 1 < TILES && nbase < n_rows) {
            int rbase = nbase + gq * 8;
#pragma unroll
            for (int u = 0; u < 8; u++) {
                int row = rbase + u;
                float v = 0.0f;
                if (row < n_rows) {
                    int sr = (mode == 2) ? __ldg(&q_rel[row]) : row;
                    v = __ldg(&src[sr * DD + j]);
                }
                pf[u] = v;
            }
        }

        // matvec: 8 rows per thread, 7 issue slots per k
        unsigned long long a01 = pack2(bias, bias), a23 = a01, a45 = a01, a67 = a01;
#pragma unroll
        for (int k = 0; k < DD; k++) {
            float w = Wst[k][j];
            unsigned long long ww = pack2(w, w);
            ulonglong2 hA = *(const ulonglong2*)&hT[gq][k * 8];
            ulonglong2 hB = *(const ulonglong2*)&hT[gq][k * 8 + 4];
            a01 = fma2(ww, hA.x, a01);
            a23 = fma2(ww, hA.y, a23);
            a45 = fma2(ww, hB.x, a45);
            a67 = fma2(ww, hB.y, a67);
        }
        float acc[8];
        unpack2(a01, acc[0], acc[1]);
        unpack2(a23, acc[2], acc[3]);
        unpack2(a45, acc[4], acc[5]);
        unpack2(a67, acc[6], acc[7]);

        // hv (own columns) re-read from hT — pf already holds next tile
        float4 hv0 = *(const float4*)&hT[gq][j * 8];
        float4 hv1 = *(const float4*)&hT[gq][j * 8 + 4];
        float hv[8] = {hv0.x, hv0.y, hv0.z, hv0.w, hv1.x, hv1.y, hv1.z, hv1.w};

        int rbase = base + gq * 8;
#pragma unroll
        for (int u = 0; u < 8; u++) {
            int row = rbase + u;
            if (row >= n_rows) continue;
            projh[row * DD + j] = __float2bfloat16(acc[u]);
            if (mode != 2) {
                float nsq = nrm[gq][0][u] + nrm[gq][1][u];
                float z2  = CC * nsq;
                float fac = tanh_ratio(z2);
                float rn2 = fac * fac * nsq;
                float ps  = 1.0f;
                if (rn2 > MN2) ps = MAXNORM * rsqrtf(rn2);
                float fp  = fac * ps;
                float x2c = fminf(rn2, MN2);
                if (mode == 1) {
                    g_hr_h[row * DD + j] = fp * hv[u];
                    if (j == 0) g_hr_y2[row] = x2c;
                } else {
                    if (j == 0) g_hs_sc[row] = make_float2(fp, x2c);
                }
            }
            if (mode == 0) zout[row * DD + j] = 0.0f;
        }
    }
}

// ---------------------------------------------------------------------------
// edge kernel: 16 lanes per group, 2 consecutive edges per group per iter,
// edge indices software-pipelined; packed bf16x2 attention math.
// ---------------------------------------------------------------------------
struct EdgeVals {
    int sub, obj;
    float s, pd;
    float4 hx, y;
    float x2, y2, fac;
};

__device__ __forceinline__ void edge_load(
    const float* __restrict__ hidden, float4 wa, int l,
    int r_idx, int rel, int sub, int obj, EdgeVals& v)
{
    v.sub = sub; v.obj = obj;

    uint2 pb = __ldg((const uint2*)g_hs_projh  + sub   * 16 + l);
    uint2 rb = __ldg((const uint2*)g_rel_projh + rel   * 16 + l);
    uint2 qb = __ldg((const uint2*)g_qr_projh  + r_idx * 16 + l);

    __nv_bfloat162 z2b; *(unsigned*)&z2b = 0u;
    __nv_bfloat162 t0 = __hmax2(__hadd2(__hadd2(*(__nv_bfloat162*)&pb.x,
                                                *(__nv_bfloat162*)&rb.x),
                                        *(__nv_bfloat162*)&qb.x), z2b);
    __nv_bfloat162 t1 = __hmax2(__hadd2(__hadd2(*(__nv_bfloat162*)&pb.y,
                                                *(__nv_bfloat162*)&rb.y),
                                        *(__nv_bfloat162*)&qb.y), z2b);
    unsigned u0 = *(unsigned*)&t0, u1 = *(unsigned*)&t1;
    float s = bflo(u0) * wa.x;
    s = fmaf(bfhi(u0), wa.y, s);
    s = fmaf(bflo(u1), wa.z, s);
    s = fmaf(bfhi(u1), wa.w, s);
    v.s = s;

    v.hx = __ldg((const float4*)hidden + sub * 16 + l);
    v.y  = __ldg((const float4*)g_hr_h + rel * 16 + l);
    float pd = v.hx.x * v.y.x;
    pd = fmaf(v.hx.y, v.y.y, pd);
    pd = fmaf(v.hx.z, v.y.z, pd);
    pd = fmaf(v.hx.w, v.y.w, pd);
    v.pd = pd;

    float2 scs = __ldg(&g_hs_sc[sub]);
    v.fac = scs.x; v.x2 = scs.y;
    v.y2  = __ldg(&g_hr_y2[rel]);
}

__device__ __forceinline__ void edge_finish(
    const EdgeVals& v, float* __restrict__ out, int l)
{
    float xy = v.fac * v.pd;
    float alpha = __fdividef(1.0f, 1.0f + __expf(-v.s));

    float A   = 1.0f + 2.0f * CC * xy + CC * v.y2;
    float B   = 1.0f - CC * v.x2;
    float den = fmaxf(1.0f + 2.0f * CC * xy + CC * CC * v.x2 * v.y2, 1e-15f);
    float inv = __fdividef(1.0f, den);
    float mm = fmaf(A * A, v.x2, fmaf(2.0f * A * B, xy, B * B * v.y2)) * inv * inv;
    mm = fmaxf(mm, 0.0f);
    float ps = 1.0f;
    if (mm > MN2) ps = MAXNORM * rsqrtf(mm);
    float z2 = CC * fminf(mm, MN2);
    float f  = artanh_ratio(z2);

    float sc = alpha * f * ps * inv;
    float sA = A * sc * v.fac;
    float sB = B * sc;

    float g0 = fmaf(sA, v.hx.x, sB * v.y.x);
    float g1 = fmaf(sA, v.hx.y, sB * v.y.y);
    float g2 = fmaf(sA, v.hx.z, sB * v.y.z);
    float g3 = fmaf(sA, v.hx.w, sB * v.y.w);

    float* dst = out + (long)v.obj * DD + l * 4;
    asm volatile("red.global.add.v4.f32 [%0], {%1,%2,%3,%4};"
                 :: "l"(dst), "f"(g0), "f"(g1), "f"(g2), "f"(g3) : "memory");
}

__global__ __launch_bounds__(256) void edge_kernel(
    const int* __restrict__ edges, const float* __restrict__ Wattn,
    const float* __restrict__ hidden, float* __restrict__ out, int n_edge)
{
    int l = threadIdx.x & 15;
    float4 wa = __ldg((const float4*)Wattn + l);
    int group  = (blockIdx.x * blockDim.x + threadIdx.x) >> 4;
    int stride = (gridDim.x * blockDim.x) >> 4;
    int npair  = (n_edge + 1) >> 1;

    int p = group;
    int2 c0a, c0b, c0c, c1a, c1b, c1c;
    if (p < npair) {
        const int2* e0 = (const int2*)edges + (long)(p * 2) * 3;
        c0a = __ldcs(e0); c0b = __ldcs(e0 + 1); c0c = __ldcs(e0 + 2);
        if (p * 2 + 1 < n_edge) {
            c1a = __ldcs(e0 + 3); c1b = __ldcs(e0 + 4); c1c = __ldcs(e0 + 5);
        } else { c1a = c0a; c1b = c0b; c1c = c0c; }
    }

    while (p < npair) {
        int2 i0a = c0a, i0b = c0b, i0c = c0c;
        int2 i1a = c1a, i1b = c1b, i1c = c1c;
        bool has1 = (p * 2 + 1) < n_edge;

        int pn = p + stride;
        if (pn < npair) {
            const int2* e0 = (const int2*)edges + (long)(pn * 2) * 3;
            c0a = __ldcs(e0); c0b = __ldcs(e0 + 1); c0c = __ldcs(e0 + 2);
            if (pn * 2 + 1 < n_edge) {
                c1a = __ldcs(e0 + 3); c1b = __ldcs(e0 + 4); c1c = __ldcs(e0 + 5);
            }
        }

        EdgeVals v0, v1;
        edge_load(hidden, wa, l, i0a.x, i0b.x, i0c.x, i0c.y, v0);
        if (has1) edge_load(hidden, wa, l, i1a.x, i1b.x, i1c.x, i1c.y, v1);
        else { v1.s = 0; v1.pd = 0; }

        float a = v0.s, b = v0.pd, c2 = v1.s, d = v1.pd;
#pragma unroll
        for (int o = 8; o; o >>= 1) {
            a  += __shfl_xor_sync(0xffffffffu, a,  o);
            b  += __shfl_xor_sync(0xffffffffu, b,  o);
            c2 += __shfl_xor_sync(0xffffffffu, c2, o);
            d  += __shfl_xor_sync(0xffffffffu, d,  o);
        }
        v0.s = a; v0.pd = b; v1.s = c2; v1.pd = d;

        edge_finish(v0, out, l);
        if (has1) edge_finish(v1, out, l);

        p = pn;
    }
}

// ---------------------------------------------------------------------------
// final: out[n] = logmap0(relu(expmap0(Wh @ agg[n])))  (in-place)
// 8 rows per 64-thread group; fused Σacc² / Σrelu(acc)² reduction.
// ---------------------------------------------------------------------------
__global__ __launch_bounds__(256) void final_kernel(
    const float* __restrict__ Wh, float* __restrict__ out, int n_node)
{
    __shared__ float Wst[DD][DD + 1];
    __shared__ __align__(16) float hT[4][DD * 8];
    __shared__ float red2[4][2][16];

    int t = threadIdx.x;
    for (int i = t; i < DD * DD; i += 256) Wst[i & 63][i >> 6] = Wh[i];

    int gq = t >> 6, j = t & 63, half = (t >> 5) & 1, lane = t & 31;

    float pf[8];
    {
        int rbase = blockIdx.x * ROWS_PER_BLOCK + gq * 8;
#pragma unroll
        for (int u = 0; u < 8; u++) {
            int row = rbase + u;
            pf[u] = (row < n_node) ? __ldg(&out[row * DD + j]) : 0.0f;
        }
    }

    for (int tile = 0; tile < TILES; tile++) {
        int base = blockIdx.x * ROWS_PER_BLOCK + tile * ROWS_PER_TILE;
        if (base >= n_node) break;

        if (tile > 0) __syncthreads();
        *(float4*)&hT[gq][j * 8]     = make_float4(pf[0], pf[1], pf[2], pf[3]);
        *(float4*)&hT[gq][j * 8 + 4] = make_float4(pf[4], pf[5], pf[6], pf[7]);
        __syncthreads();

        int nbase = base + ROWS_PER_TILE;
        if (tile + 1 < TILES && nbase < n_node) {
            int rbase = nbase + gq * 8;
#pragma unroll
            for (int u = 0; u < 8; u++) {
                int row = rbase + u;
                pf[u] = (row < n_node) ? __ldg(&out[row * DD + j]) : 0.0f;
            }
        }

        unsigned long long a01 = 0ull, a23 = 0ull, a45 = 0ull, a67 = 0ull;
#pragma unroll
        for (int k = 0; k < DD; k++) {
            float w = Wst[k][j];
            unsigned long long ww = pack2(w, w);
            ulonglong2 hA = *(const ulonglong2*)&hT[gq][k * 8];
            ulonglong2 hB = *(const ulonglong2*)&hT[gq][k * 8 + 4];
            a01 = fma2(ww, hA.x, a01);
            a23 = fma2(ww, hA.y, a23);
            a45 = fma2(ww, hB.x, a45);
            a67 = fma2(ww, hB.y, a67);
        }
        float acc[8];
        unpack2(a01, acc[0], acc[1]);
        unpack2(a23, acc[2], acc[3]);
        unpack2(a45, acc[4], acc[5]);
        unpack2(a67, acc[6], acc[7]);

        // fused reduction: Σacc² and Σmax(acc,0)² per row
        float sa[8], sp[8];
#pragma unroll
        for (int u = 0; u < 8; u++) {
            float ap = fmaxf(acc[u], 0.0f);
            sa[u] = acc[u] * acc[u];
            sp[u] = ap * ap;
        }
#pragma unroll
        for (int o = 16; o; o >>= 1) {
#pragma unroll
            for (int u = 0; u < 8; u++) {
                sa[u] += __shfl_xor_sync(0xffffffffu, sa[u], o);
                sp[u] += __shfl_xor_sync(0xffffffffu, sp[u], o);
            }
        }
        if (lane == 0) {
#pragma unroll
            for (int u = 0; u < 8; u++) {
                red2[gq][half][u]     = sa[u];
                red2[gq][half][8 + u] = sp[u];
            }
        }
        __syncthreads();

        int rbase = base + gq * 8;
#pragma unroll
        for (int u = 0; u < 8; u++) {
            int row = rbase + u;
            if (row >= n_node) continue;
            float nv2 = red2[gq][0][u]     + red2[gq][1][u];
            float sp2 = red2[gq][0][8 + u] + red2[gq][1][8 + u];
            float z2  = CC * nv2;
            float fac = tanh_ratio(z2);
            float rn2 = fac * fac * nv2;
            float ps  = 1.0f;
            if (rn2 > MN2) ps = MAXNORM * rsqrtf(rn2);
            float fp  = fac * ps;
            float na2 = fp * fp * sp2;               // ||relu(expmap0)||^2
            float gg  = artanh_ratio(CC * na2);
            out[row * DD + j] = fp * fmaxf(acc[u], 0.0f) * gg;
        }
    }
}

// ---------------------------------------------------------------------------
extern "C" void kernel_launch(void* const* d_in, const int* in_sizes, int n_in,
                              void* d_out, int out_size)
{
    const float* hidden = (const float*)d_in[0];
    const int*   q_rel  = (const int*)  d_in[1];
    const int*   edges  = (const int*)  d_in[2];
    const float* rela   = (const float*)d_in[3];
    const float* Ws     = (const float*)d_in[4];
    const float* Wr     = (const float*)d_in[5];
    const float* Wqr    = (const float*)d_in[6];
    const float* Wqr_b  = (const float*)d_in[7];
    const float* Wattn  = (const float*)d_in[8];
    const float* Wh     = (const float*)d_in[9];
    float* out = (float*)d_out;

    int n_node  = in_sizes[0] / DD;
    int Bn      = in_sizes[1];
    int n_edge  = in_sizes[2] / 6;
    int n_vocab = in_sizes[3] / DD;

    int nb0 = (n_node  + ROWS_PER_BLOCK - 1) / ROWS_PER_BLOCK;
    int nb1 = (n_vocab + ROWS_PER_BLOCK - 1) / ROWS_PER_BLOCK;
    int nb2 = (Bn      + ROWS_PER_BLOCK - 1) / ROWS_PER_BLOCK;

    prep_all<<<nb0 + nb1 + nb2, 256>>>(Ws, Wr, Wqr, hidden, rela, q_rel, Wqr_b,
                                       out, n_node, n_vocab, Bn, nb0, nb1);

    edge_kernel<<<2368, 256>>>(edges, Wattn, hidden, out, n_edge);

    final_kernel<<<(n_node + ROWS_PER_BLOCK - 1) / ROWS_PER_BLOCK, 256>>>(Wh, out, n_node);
}

// round 8
// speedup vs baseline: 1.0307x; 1.0307x over previous
#include <cuda_runtime.h>
#include <cuda_bf16.h>
#include <math.h>

// ---------------------------------------------------------------------------
// GNNModel: hyperbolic GNN message passing (c = 1e-6)
// ---------------------------------------------------------------------------

#define MAX_NODE 100000
#define MAX_VOCAB 512
#define MAX_B 256
#define DD 64
#define TILES 4
#define ROWS_PER_TILE 16
#define ROWS_PER_BLOCK (TILES * ROWS_PER_TILE)   // 64

// attention tables in bf16 (only feed sigmoid(relu(.)@Wattn) — error << 1e-3)
__device__ __align__(16) __nv_bfloat16 g_hs_projh [MAX_NODE * DD];
__device__ __align__(16) __nv_bfloat16 g_rel_projh[MAX_VOCAB * DD];
__device__ __align__(16) __nv_bfloat16 g_qr_projh [MAX_B * DD];
__device__ float2 g_hs_sc [MAX_NODE];        // (fac*ps, ||expmap0||^2 clamped)
__device__ float  g_hr_h  [MAX_VOCAB * DD];  // expmap0(rela_embed[r]) projected
__device__ float  g_hr_y2 [MAX_VOCAB];       // ||hr_h||^2

#define SC 1.0e-3f                    // sqrt(c), c = 1e-6
#define CC 1.0e-6f
#define MAXNORM (0.996f / SC)
#define MN2 (MAXNORM * MAXNORM)

// ---- packed f32x2 helpers ----
__device__ __forceinline__ unsigned long long pack2(float a, float b) {
    unsigned long long r;
    asm("mov.b64 %0, {%1, %2};" : "=l"(r)
        : "r"(__float_as_uint(a)), "r"(__float_as_uint(b)));
    return r;
}
__device__ __forceinline__ void unpack2(unsigned long long v, float& a, float& b) {
    unsigned lo, hi;
    asm("mov.b64 {%0, %1}, %2;" : "=r"(lo), "=r"(hi) : "l"(v));
    a = __uint_as_float(lo); b = __uint_as_float(hi);
}
__device__ __forceinline__ unsigned long long fma2(
    unsigned long long a, unsigned long long b, unsigned long long c) {
    unsigned long long d;
    asm("fma.rn.f32x2 %0, %1, %2, %3;" : "=l"(d) : "l"(a), "l"(b), "l"(c));
    return d;
}
// bf16 pair (packed in u32) -> two f32, pure ALU
__device__ __forceinline__ float bflo(unsigned u) { return __uint_as_float(u << 16); }
__device__ __forceinline__ float bfhi(unsigned u) { return __uint_as_float(u & 0xffff0000u); }

// artanh(z)/z as poly in z^2 (valid z^2 < 0.09, guarded fallback above)
__device__ __forceinline__ float artanh_ratio(float z2) {
    float f = fmaf(z2, fmaf(z2, fmaf(z2, fmaf(z2, 1.0f/9.0f, 1.0f/7.0f),
                                     0.2f), 1.0f/3.0f), 1.0f);
    if (z2 > 0.09f) {
        float z = sqrtf(z2);
        float zc = fminf(z, 1.0f - 1e-5f);
        f = 0.5f * (log1pf(zc) - log1pf(-zc)) / z;
    }
    return f;
}
// tanh(z)/z as poly in z^2 (valid z^2 < 0.09, guarded)
__device__ __forceinline__ float tanh_ratio(float z2) {
    float f = fmaf(z2, fmaf(z2, fmaf(z2, -17.0f/315.0f, 2.0f/15.0f),
                            -1.0f/3.0f), 1.0f);
    if (z2 > 0.09f) {
        float z = sqrtf(z2);
        f = tanhf(fminf(z, 15.0f)) / z;
    }
    return f;
}

// ---------------------------------------------------------------------------
// fused prep: one launch; blockIdx routes to mode. 64 rows/block, 16/tile,
// 4 rows per 64-thread group. Thread owns column j of its group's 4 rows:
// staging = 1 STS.128; norms via shuffle at staging; loop = 2 LDS + 2 FFMA2.
// ---------------------------------------------------------------------------
__global__ __launch_bounds__(256) void prep_all(
    const float* __restrict__ Ws, const float* __restrict__ Wr,
    const float* __restrict__ Wqr, const float* __restrict__ hidden,
    const float* __restrict__ rela, const int* __restrict__ q_rel,
    const float* __restrict__ Wqr_b,
    int n_node, int n_vocab, int nB, int nb0, int nb1)
{
    __shared__ float Wst[DD][DD + 1];                 // Wst[k][j] = W[j*64+k]
    __shared__ __align__(16) float hT[4][DD * 4];     // hT[g][k*4 + r]
    __shared__ float nrm[4][2][4];

    int mode, bidx, n_rows;
    const float* W; const float* src;
    if ((int)blockIdx.x < nb0) {
        mode = 0; bidx = blockIdx.x; W = Ws; src = hidden; n_rows = n_node;
    } else if ((int)blockIdx.x < nb0 + nb1) {
        mode = 1; bidx = blockIdx.x - nb0; W = Wr; src = rela; n_rows = n_vocab;
    } else {
        mode = 2; bidx = blockIdx.x - nb0 - nb1; W = Wqr; src = rela; n_rows = nB;
    }

    int t = threadIdx.x;
    for (int i = t; i < DD * DD; i += 256) Wst[i & 63][i >> 6] = W[i];

    __nv_bfloat16* projh = (mode == 0) ? g_hs_projh :
                           (mode == 1) ? g_rel_projh : g_qr_projh;

    int g = t >> 6, j = t & 63, half = (t >> 5) & 1, lane = t & 31;
    float bias = (mode == 2) ? Wqr_b[j] : 0.0f;

    float pf[4];
    // prefetch tile 0: thread owns column j of rows base + g*4 + u
    {
        int rbase = bidx * ROWS_PER_BLOCK + g * 4;
#pragma unroll
        for (int u = 0; u < 4; u++) {
            int row = rbase + u;
            float v = 0.0f;
            if (row < n_rows) {
                int sr = (mode == 2) ? __ldg(&q_rel[row]) : row;
                v = __ldg(&src[sr * DD + j]);
            }
            pf[u] = v;
        }
    }

    for (int tile = 0; tile < TILES; tile++) {
        int base = bidx * ROWS_PER_BLOCK + tile * ROWS_PER_TILE;
        if (base >= n_rows) break;

        if (tile > 0) __syncthreads();     // hT/nrm free from previous tile
        *(float4*)&hT[g][j * 4] = make_float4(pf[0], pf[1], pf[2], pf[3]);

        // per-row ||u||^2 via shuffle at staging (not in the matvec loop)
        if (mode != 2) {
            float nv0 = pf[0]*pf[0], nv1 = pf[1]*pf[1],
                  nv2 = pf[2]*pf[2], nv3 = pf[3]*pf[3];
#pragma unroll
            for (int o = 16; o; o >>= 1) {
                nv0 += __shfl_xor_sync(0xffffffffu, nv0, o);
                nv1 += __shfl_xor_sync(0xffffffffu, nv1, o);
                nv2 += __shfl_xor_sync(0xffffffffu, nv2, o);
                nv3 += __shfl_xor_sync(0xffffffffu, nv3, o);
            }
            if (lane == 0) {
                nrm[g][half][0] = nv0; nrm[g][half][1] = nv1;
                nrm[g][half][2] = nv2; nrm[g][half][3] = nv3;
            }
        }
        __syncthreads();

        // prefetch next tile (LDG latency hidden under compute)
        int nbase = base + ROWS_PER_TILE;
        if (tile + 1 < TILES && nbase < n_rows) {
            int rbase = nbase + g * 4;
#pragma unroll
            for (int u = 0; u < 4; u++) {
                int row = rbase + u;
                float v = 0.0f;
                if (row < n_rows) {
                    int sr = (mode == 2) ? __ldg(&q_rel[row]) : row;
                    v = __ldg(&src[sr * DD + j]);
                }
                pf[u] = v;
            }
        }

        // matvec: 2 LDS + 2 FFMA2 per k for 4 rows
        unsigned long long a01 = pack2(bias, bias), a23 = a01;
#pragma unroll
        for (int k = 0; k < DD; k++) {
            float w = Wst[k][j];
            unsigned long long ww = pack2(w, w);
            ulonglong2 hh = *(const ulonglong2*)&hT[g][k * 4];
            a01 = fma2(ww, hh.x, a01);
            a23 = fma2(ww, hh.y, a23);
        }
        float acc[4];
        unpack2(a01, acc[0], acc[1]);
        unpack2(a23, acc[2], acc[3]);

        int rbase = base + g * 4;
#pragma unroll
        for (int u = 0; u < 4; u++) {
            int row = rbase + u;
            if (row >= n_rows) continue;
            projh[row * DD + j] = __float2bfloat16(acc[u]);
        }

        if (mode == 1) {
            // own columns of this tile (hT still valid until next stage)
            float4 hv = *(const float4*)&hT[g][j * 4];
            float hva[4] = {hv.x, hv.y, hv.z, hv.w};
#pragma unroll
            for (int u = 0; u < 4; u++) {
                int row = rbase + u;
                if (row >= n_rows) continue;
                float nsq = nrm[g][0][u] + nrm[g][1][u];
                float fac = tanh_ratio(CC * nsq);
                float rn2 = fac * fac * nsq;
                float ps  = 1.0f;
                if (rn2 > MN2) ps = MAXNORM * rsqrtf(rn2);
                float fp  = fac * ps;
                g_hr_h[row * DD + j] = fp * hva[u];
                if (j == 0) g_hr_y2[row] = fminf(rn2, MN2);
            }
        } else if (mode == 0 && j == 0) {
#pragma unroll
            for (int u = 0; u < 4; u++) {
                int row = rbase + u;
                if (row >= n_rows) continue;
                float nsq = nrm[g][0][u] + nrm[g][1][u];
                float fac = tanh_ratio(CC * nsq);
                float rn2 = fac * fac * nsq;
                float ps  = 1.0f;
                if (rn2 > MN2) ps = MAXNORM * rsqrtf(rn2);
                g_hs_sc[row] = make_float2(fac * ps, fminf(rn2, MN2));
            }
        }
    }
}

// ---------------------------------------------------------------------------
// edge kernel: 16 lanes per group, 2 consecutive edges per group per iter,
// edge indices software-pipelined; packed bf16x2 attention math.
// ---------------------------------------------------------------------------
struct EdgeVals {
    int sub, obj;
    float s, pd;
    float4 hx, y;
    float x2, y2, fac;
};

__device__ __forceinline__ void edge_load(
    const float* __restrict__ hidden, float4 wa, int l,
    int r_idx, int rel, int sub, int obj, EdgeVals& v)
{
    v.sub = sub; v.obj = obj;

    uint2 pb = __ldg((const uint2*)g_hs_projh  + sub   * 16 + l);
    uint2 rb = __ldg((const uint2*)g_rel_projh + rel   * 16 + l);
    uint2 qb = __ldg((const uint2*)g_qr_projh  + r_idx * 16 + l);

    __nv_bfloat162 z2b; *(unsigned*)&z2b = 0u;
    __nv_bfloat162 t0 = __hmax2(__hadd2(__hadd2(*(__nv_bfloat162*)&pb.x,
                                                *(__nv_bfloat162*)&rb.x),
                                        *(__nv_bfloat162*)&qb.x), z2b);
    __nv_bfloat162 t1 = __hmax2(__hadd2(__hadd2(*(__nv_bfloat162*)&pb.y,
                                                *(__nv_bfloat162*)&rb.y),
                                        *(__nv_bfloat162*)&qb.y), z2b);
    unsigned u0 = *(unsigned*)&t0, u1 = *(unsigned*)&t1;
    float s = bflo(u0) * wa.x;
    s = fmaf(bfhi(u0), wa.y, s);
    s = fmaf(bflo(u1), wa.z, s);
    s = fmaf(bfhi(u1), wa.w, s);
    v.s = s;

    v.hx = __ldg((const float4*)hidden + sub * 16 + l);
    v.y  = __ldg((const float4*)g_hr_h + rel * 16 + l);
    float pd = v.hx.x * v.y.x;
    pd = fmaf(v.hx.y, v.y.y, pd);
    pd = fmaf(v.hx.z, v.y.z, pd);
    pd = fmaf(v.hx.w, v.y.w, pd);
    v.pd = pd;

    float2 scs = __ldg(&g_hs_sc[sub]);
    v.fac = scs.x; v.x2 = scs.y;
    v.y2  = __ldg(&g_hr_y2[rel]);
}

__device__ __forceinline__ void edge_finish(
    const EdgeVals& v, float* __restrict__ out, int l)
{
    float xy = v.fac * v.pd;
    float alpha = __fdividef(1.0f, 1.0f + __expf(-v.s));

    float A   = 1.0f + 2.0f * CC * xy + CC * v.y2;
    float B   = 1.0f - CC * v.x2;
    float den = fmaxf(1.0f + 2.0f * CC * xy + CC * CC * v.x2 * v.y2, 1e-15f);
    float inv = __fdividef(1.0f, den);
    float mm = fmaf(A * A, v.x2, fmaf(2.0f * A * B, xy, B * B * v.y2)) * inv * inv;
    mm = fmaxf(mm, 0.0f);
    float ps = 1.0f;
    if (mm > MN2) ps = MAXNORM * rsqrtf(mm);
    float z2 = CC * fminf(mm, MN2);
    float f  = artanh_ratio(z2);

    float sc = alpha * f * ps * inv;
    float sA = A * sc * v.fac;
    float sB = B * sc;

    float g0 = fmaf(sA, v.hx.x, sB * v.y.x);
    float g1 = fmaf(sA, v.hx.y, sB * v.y.y);
    float g2 = fmaf(sA, v.hx.z, sB * v.y.z);
    float g3 = fmaf(sA, v.hx.w, sB * v.y.w);

    float* dst = out + (long)v.obj * DD + l * 4;
    asm volatile("red.global.add.v4.f32 [%0], {%1,%2,%3,%4};"
                 :: "l"(dst), "f"(g0), "f"(g1), "f"(g2), "f"(g3) : "memory");
}

__global__ __launch_bounds__(256) void edge_kernel(
    const int* __restrict__ edges, const float* __restrict__ Wattn,
    const float* __restrict__ hidden, float* __restrict__ out, int n_edge)
{
    int l = threadIdx.x & 15;
    float4 wa = __ldg((const float4*)Wattn + l);
    int group  = (blockIdx.x * blockDim.x + threadIdx.x) >> 4;
    int stride = (gridDim.x * blockDim.x) >> 4;
    int npair  = (n_edge + 1) >> 1;

    int p = group;
    int2 c0a, c0b, c0c, c1a, c1b, c1c;
    if (p < npair) {
        const int2* e0 = (const int2*)edges + (long)(p * 2) * 3;
        c0a = __ldcs(e0); c0b = __ldcs(e0 + 1); c0c = __ldcs(e0 + 2);
        if (p * 2 + 1 < n_edge) {
            c1a = __ldcs(e0 + 3); c1b = __ldcs(e0 + 4); c1c = __ldcs(e0 + 5);
        } else { c1a = c0a; c1b = c0b; c1c = c0c; }
    }

    while (p < npair) {
        int2 i0a = c0a, i0b = c0b, i0c = c0c;
        int2 i1a = c1a, i1b = c1b, i1c = c1c;
        bool has1 = (p * 2 + 1) < n_edge;

        int pn = p + stride;
        if (pn < npair) {
            const int2* e0 = (const int2*)edges + (long)(pn * 2) * 3;
            c0a = __ldcs(e0); c0b = __ldcs(e0 + 1); c0c = __ldcs(e0 + 2);
            if (pn * 2 + 1 < n_edge) {
                c1a = __ldcs(e0 + 3); c1b = __ldcs(e0 + 4); c1c = __ldcs(e0 + 5);
            }
        }

        EdgeVals v0, v1;
        edge_load(hidden, wa, l, i0a.x, i0b.x, i0c.x, i0c.y, v0);
        if (has1) edge_load(hidden, wa, l, i1a.x, i1b.x, i1c.x, i1c.y, v1);
        else { v1.s = 0; v1.pd = 0; }

        float a = v0.s, b = v0.pd, c2 = v1.s, d = v1.pd;
#pragma unroll
        for (int o = 8; o; o >>= 1) {
            a  += __shfl_xor_sync(0xffffffffu, a,  o);
            b  += __shfl_xor_sync(0xffffffffu, b,  o);
            c2 += __shfl_xor_sync(0xffffffffu, c2, o);
            d  += __shfl_xor_sync(0xffffffffu, d,  o);
        }
        v0.s = a; v0.pd = b; v1.s = c2; v1.pd = d;

        edge_finish(v0, out, l);
        if (has1) edge_finish(v1, out, l);

        p = pn;
    }
}

// ---------------------------------------------------------------------------
// final: out[n] = logmap0(relu(expmap0(Wh @ agg[n])))  (in-place)
// 4 rows per 64-thread group; fused Σacc² / Σrelu(acc)² single reduction.
// ---------------------------------------------------------------------------
__global__ __launch_bounds__(256) void final_kernel(
    const float* __restrict__ Wh, float* __restrict__ out, int n_node)
{
    __shared__ float Wst[DD][DD + 1];
    __shared__ __align__(16) float hT[4][DD * 4];
    __shared__ float red2[4][2][8];

    int t = threadIdx.x;
    for (int i = t; i < DD * DD; i += 256) Wst[i & 63][i >> 6] = Wh[i];

    int g = t >> 6, j = t & 63, half = (t >> 5) & 1, lane = t & 31;

    float pf[4];
    {
        int rbase = blockIdx.x * ROWS_PER_BLOCK + g * 4;
#pragma unroll
        for (int u = 0; u < 4; u++) {
            int row = rbase + u;
            pf[u] = (row < n_node) ? __ldg(&out[row * DD + j]) : 0.0f;
        }
    }

    for (int tile = 0; tile < TILES; tile++) {
        int base = blockIdx.x * ROWS_PER_BLOCK + tile * ROWS_PER_TILE;
        if (base >= n_node) break;

        if (tile > 0) __syncthreads();
        *(float4*)&hT[g][j * 4] = make_float4(pf[0], pf[1], pf[2], pf[3]);
        __syncthreads();

        int nbase = base + ROWS_PER_TILE;
        if (tile + 1 < TILES && nbase < n_node) {
            int rbase = nbase + g * 4;
#pragma unroll
            for (int u = 0; u < 4; u++) {
                int row = rbase + u;
                pf[u] = (row < n_node) ? __ldg(&out[row * DD + j]) : 0.0f;
            }
        }

        unsigned long long a01 = 0ull, a23 = 0ull;
#pragma unroll
        for (int k = 0; k < DD; k++) {
            float w = Wst[k][j];
            unsigned long long ww = pack2(w, w);
            ulonglong2 hh = *(const ulonglong2*)&hT[g][k * 4];
            a01 = fma2(ww, hh.x, a01);
            a23 = fma2(ww, hh.y, a23);
        }
        float acc[4];
        unpack2(a01, acc[0], acc[1]);
        unpack2(a23, acc[2], acc[3]);

        // fused reduction: Σacc² and Σmax(acc,0)² per row
        float sa[4], sp[4];
#pragma unroll
        for (int u = 0; u < 4; u++) {
            float ap = fmaxf(acc[u], 0.0f);
            sa[u] = acc[u] * acc[u];
            sp[u] = ap * ap;
        }
#pragma unroll
        for (int o = 16; o; o >>= 1) {
#pragma unroll
            for (int u = 0; u < 4; u++) {
                sa[u] += __shfl_xor_sync(0xffffffffu, sa[u], o);
                sp[u] += __shfl_xor_sync(0xffffffffu, sp[u], o);
            }
        }
        if (lane == 0) {
#pragma unroll
            for (int u = 0; u < 4; u++) {
                red2[g][half][u]     = sa[u];
                red2[g][half][4 + u] = sp[u];
            }
        }
        __syncthreads();

        int rbase = base + g * 4;
#pragma unroll
        for (int u = 0; u < 4; u++) {
            int row = rbase + u;
            if (row >= n_node) continue;
            float nv2 = red2[g][0][u]     + red2[g][1][u];
            float sp2 = red2[g][0][4 + u] + red2[g][1][4 + u];
            float fac = tanh_ratio(CC * nv2);
            float rn2 = fac * fac * nv2;
            float ps  = 1.0f;
            if (rn2 > MN2) ps = MAXNORM * rsqrtf(rn2);
            float fp  = fac * ps;
            float na2 = fp * fp * sp2;               // ||relu(expmap0)||^2
            float gg  = artanh_ratio(CC * na2);
            out[row * DD + j] = fp * fmaxf(acc[u], 0.0f) * gg;
        }
    }
}

// ---------------------------------------------------------------------------
extern "C" void kernel_launch(void* const* d_in, const int* in_sizes, int n_in,
                              void* d_out, int out_size)
{
    const float* hidden = (const float*)d_in[0];
    const int*   q_rel  = (const int*)  d_in[1];
    const int*   edges  = (const int*)  d_in[2];
    const float* rela   = (const float*)d_in[3];
    const float* Ws     = (const float*)d_in[4];
    const float* Wr     = (const float*)d_in[5];
    const float* Wqr    = (const float*)d_in[6];
    const float* Wqr_b  = (const float*)d_in[7];
    const float* Wattn  = (const float*)d_in[8];
    const float* Wh     = (const float*)d_in[9];
    float* out = (float*)d_out;

    int n_node  = in_sizes[0] / DD;
    int Bn      = in_sizes[1];
    int n_edge  = in_sizes[2] / 6;
    int n_vocab = in_sizes[3] / DD;

    // zero accumulator (graph-capturable memset node)
    cudaMemsetAsync(out, 0, (size_t)out_size * sizeof(float));

    int nb0 = (n_node  + ROWS_PER_BLOCK - 1) / ROWS_PER_BLOCK;
    int nb1 = (n_vocab + ROWS_PER_BLOCK - 1) / ROWS_PER_BLOCK;
    int nb2 = (Bn      + ROWS_PER_BLOCK - 1) / ROWS_PER_BLOCK;

    prep_all<<<nb0 + nb1 + nb2, 256>>>(Ws, Wr, Wqr, hidden, rela, q_rel, Wqr_b,
                                       n_node, n_vocab, Bn, nb0, nb1);

    edge_kernel<<<2368, 256>>>(edges, Wattn, hidden, out, n_edge);

    final_kernel<<<(n_node + ROWS_PER_BLOCK - 1) / ROWS_PER_BLOCK, 256>>>(Wh, out, n_node);
}

// round 9
// speedup vs baseline: 1.2196x; 1.1832x over previous
#include <cuda_runtime.h>
#include <cuda_bf16.h>
#include <math.h>

// ---------------------------------------------------------------------------
// GNNModel: hyperbolic GNN message passing (c = 1e-6)
//
// With c=1e-6 and data scale 0.1, expmap0/mobius/logmap0 in the EDGE path are
// identity to O(1e-6) relative (tolerance is 1e-3):
//   mess2 = logmap0(project(mobius_add(expmap0(hs), expmap0(hr)))) 
//         = (hs + hr) * (1 + O(c*(|hs|^2+|hr|^2)))      [|.|~0.8]
// so message = alpha * (hidden[sub] + rela_embed[rel]).
// The FINAL per-node transform keeps exact (polynomial) math since ||agg||^2
// can be O(10^3), where corrections reach ~1e-4.
// ---------------------------------------------------------------------------

#define MAX_NODE 100000
#define MAX_VOCAB 512
#define MAX_B 256
#define DD 64
#define TILES 4
#define ROWS_PER_TILE 16
#define ROWS_PER_BLOCK (TILES * ROWS_PER_TILE)   // 64

// attention tables in bf16 (only feed sigmoid(relu(.)@Wattn) — error << 1e-3)
__device__ __align__(16) __nv_bfloat16 g_hs_projh [MAX_NODE * DD];
__device__ __align__(16) __nv_bfloat16 g_rel_projh[MAX_VOCAB * DD];
__device__ __align__(16) __nv_bfloat16 g_qr_projh [MAX_B * DD];

#define SC 1.0e-3f                    // sqrt(c), c = 1e-6
#define CC 1.0e-6f
#define MAXNORM (0.996f / SC)
#define MN2 (MAXNORM * MAXNORM)

// ---- packed f32x2 helpers ----
__device__ __forceinline__ unsigned long long pack2(float a, float b) {
    unsigned long long r;
    asm("mov.b64 %0, {%1, %2};" : "=l"(r)
        : "r"(__float_as_uint(a)), "r"(__float_as_uint(b)));
    return r;
}
__device__ __forceinline__ void unpack2(unsigned long long v, float& a, float& b) {
    unsigned lo, hi;
    asm("mov.b64 {%0, %1}, %2;" : "=r"(lo), "=r"(hi) : "l"(v));
    a = __uint_as_float(lo); b = __uint_as_float(hi);
}
__device__ __forceinline__ unsigned long long fma2(
    unsigned long long a, unsigned long long b, unsigned long long c) {
    unsigned long long d;
    asm("fma.rn.f32x2 %0, %1, %2, %3;" : "=l"(d) : "l"(a), "l"(b), "l"(c));
    return d;
}
// bf16 pair (packed in u32) -> two f32, pure ALU
__device__ __forceinline__ float bflo(unsigned u) { return __uint_as_float(u << 16); }
__device__ __forceinline__ float bfhi(unsigned u) { return __uint_as_float(u & 0xffff0000u); }

// artanh(z)/z as poly in z^2 (valid z^2 < 0.09, guarded fallback above)
__device__ __forceinline__ float artanh_ratio(float z2) {
    float f = fmaf(z2, fmaf(z2, fmaf(z2, fmaf(z2, 1.0f/9.0f, 1.0f/7.0f),
                                     0.2f), 1.0f/3.0f), 1.0f);
    if (z2 > 0.09f) {
        float z = sqrtf(z2);
        float zc = fminf(z, 1.0f - 1e-5f);
        f = 0.5f * (log1pf(zc) - log1pf(-zc)) / z;
    }
    return f;
}
// tanh(z)/z as poly in z^2 (valid z^2 < 0.09, guarded)
__device__ __forceinline__ float tanh_ratio(float z2) {
    float f = fmaf(z2, fmaf(z2, fmaf(z2, -17.0f/315.0f, 2.0f/15.0f),
                            -1.0f/3.0f), 1.0f);
    if (z2 > 0.09f) {
        float z = sqrtf(z2);
        f = tanhf(fminf(z, 15.0f)) / z;
    }
    return f;
}

// ---------------------------------------------------------------------------
// fused prep: one launch; blockIdx routes to mode. Pure GEMV -> bf16 table.
// 64 rows/block, 16/tile, 4 rows per 64-thread group. Thread owns column j
// of its group's 4 rows: staging = 1 STS.128; loop = 2 LDS + 2 FFMA2 per k.
// ---------------------------------------------------------------------------
__global__ __launch_bounds__(256) void prep_all(
    const float* __restrict__ Ws, const float* __restrict__ Wr,
    const float* __restrict__ Wqr, const float* __restrict__ hidden,
    const float* __restrict__ rela, const int* __restrict__ q_rel,
    const float* __restrict__ Wqr_b,
    int n_node, int n_vocab, int nB, int nb0, int nb1)
{
    __shared__ float Wst[DD][DD + 1];                 // Wst[k][j] = W[j*64+k]
    __shared__ __align__(16) float hT[4][DD * 4];     // hT[g][k*4 + r]

    int mode, bidx, n_rows;
    const float* W; const float* src;
    if ((int)blockIdx.x < nb0) {
        mode = 0; bidx = blockIdx.x; W = Ws; src = hidden; n_rows = n_node;
    } else if ((int)blockIdx.x < nb0 + nb1) {
        mode = 1; bidx = blockIdx.x - nb0; W = Wr; src = rela; n_rows = n_vocab;
    } else {
        mode = 2; bidx = blockIdx.x - nb0 - nb1; W = Wqr; src = rela; n_rows = nB;
    }

    int t = threadIdx.x;
    for (int i = t; i < DD * DD; i += 256) Wst[i & 63][i >> 6] = W[i];

    __nv_bfloat16* projh = (mode == 0) ? g_hs_projh :
                           (mode == 1) ? g_rel_projh : g_qr_projh;

    int g = t >> 6, j = t & 63;
    float bias = (mode == 2) ? Wqr_b[j] : 0.0f;

    float pf[4];
    // prefetch tile 0: thread owns column j of rows base + g*4 + u
    {
        int rbase = bidx * ROWS_PER_BLOCK + g * 4;
#pragma unroll
        for (int u = 0; u < 4; u++) {
            int row = rbase + u;
            float v = 0.0f;
            if (row < n_rows) {
                int sr = (mode == 2) ? __ldg(&q_rel[row]) : row;
                v = __ldg(&src[sr * DD + j]);
            }
            pf[u] = v;
        }
    }

    for (int tile = 0; tile < TILES; tile++) {
        int base = bidx * ROWS_PER_BLOCK + tile * ROWS_PER_TILE;
        if (base >= n_rows) break;

        if (tile > 0) __syncthreads();     // hT free from previous tile
        *(float4*)&hT[g][j * 4] = make_float4(pf[0], pf[1], pf[2], pf[3]);
        __syncthreads();

        // prefetch next tile (LDG latency hidden under compute)
        int nbase = base + ROWS_PER_TILE;
        if (tile + 1 < TILES && nbase < n_rows) {
            int rbase = nbase + g * 4;
#pragma unroll
            for (int u = 0; u < 4; u++) {
                int row = rbase + u;
                float v = 0.0f;
                if (row < n_rows) {
                    int sr = (mode == 2) ? __ldg(&q_rel[row]) : row;
                    v = __ldg(&src[sr * DD + j]);
                }
                pf[u] = v;
            }
        }

        // matvec: 2 LDS + 2 FFMA2 per k for 4 rows
        unsigned long long a01 = pack2(bias, bias), a23 = a01;
#pragma unroll
        for (int k = 0; k < DD; k++) {
            float w = Wst[k][j];
            unsigned long long ww = pack2(w, w);
            ulonglong2 hh = *(const ulonglong2*)&hT[g][k * 4];
            a01 = fma2(ww, hh.x, a01);
            a23 = fma2(ww, hh.y, a23);
        }
        float acc[4];
        unpack2(a01, acc[0], acc[1]);
        unpack2(a23, acc[2], acc[3]);

        int rbase = base + g * 4;
#pragma unroll
        for (int u = 0; u < 4; u++) {
            int row = rbase + u;
            if (row >= n_rows) continue;
            projh[row * DD + j] = __float2bfloat16(acc[u]);
        }
    }
}

// ---------------------------------------------------------------------------
// edge kernel: 16 lanes per group, 2 consecutive edges per group per iter,
// edge indices software-pipelined; packed bf16x2 attention math.
// message = sigmoid(attn) * (hidden[sub] + rela_embed[rel])   [see header]
// ---------------------------------------------------------------------------
struct EdgeVals {
    int obj;
    float s;
    float4 hx, y;
};

__device__ __forceinline__ void edge_load(
    const float* __restrict__ hidden, const float* __restrict__ rela,
    float4 wa, int l, int r_idx, int rel, int sub, int obj, EdgeVals& v)
{
    v.obj = obj;

    uint2 pb = __ldg((const uint2*)g_hs_projh  + sub   * 16 + l);
    uint2 rb = __ldg((const uint2*)g_rel_projh + rel   * 16 + l);
    uint2 qb = __ldg((const uint2*)g_qr_projh  + r_idx * 16 + l);

    __nv_bfloat162 z2b; *(unsigned*)&z2b = 0u;
    __nv_bfloat162 t0 = __hmax2(__hadd2(__hadd2(*(__nv_bfloat162*)&pb.x,
                                                *(__nv_bfloat162*)&rb.x),
                                        *(__nv_bfloat162*)&qb.x), z2b);
    __nv_bfloat162 t1 = __hmax2(__hadd2(__hadd2(*(__nv_bfloat162*)&pb.y,
                                                *(__nv_bfloat162*)&rb.y),
                                        *(__nv_bfloat162*)&qb.y), z2b);
    unsigned u0 = *(unsigned*)&t0, u1 = *(unsigned*)&t1;
    float s = bflo(u0) * wa.x;
    s = fmaf(bfhi(u0), wa.y, s);
    s = fmaf(bflo(u1), wa.z, s);
    s = fmaf(bfhi(u1), wa.w, s);
    v.s = s;

    v.hx = __ldg((const float4*)hidden + sub * 16 + l);
    v.y  = __ldg((const float4*)rela   + rel * 16 + l);
}

__device__ __forceinline__ void edge_finish(
    const EdgeVals& v, float* __restrict__ out, int l)
{
    float alpha = __fdividef(1.0f, 1.0f + __expf(-v.s));

    float g0 = alpha * (v.hx.x + v.y.x);
    float g1 = alpha * (v.hx.y + v.y.y);
    float g2 = alpha * (v.hx.z + v.y.z);
    float g3 = alpha * (v.hx.w + v.y.w);

    float* dst = out + (long)v.obj * DD + l * 4;
    asm volatile("red.global.add.v4.f32 [%0], {%1,%2,%3,%4};"
                 :: "l"(dst), "f"(g0), "f"(g1), "f"(g2), "f"(g3) : "memory");
}

__global__ __launch_bounds__(256) void edge_kernel(
    const int* __restrict__ edges, const float* __restrict__ Wattn,
    const float* __restrict__ hidden, const float* __restrict__ rela,
    float* __restrict__ out, int n_edge)
{
    int l = threadIdx.x & 15;
    float4 wa = __ldg((const float4*)Wattn + l);
    int group  = (blockIdx.x * blockDim.x + threadIdx.x) >> 4;
    int stride = (gridDim.x * blockDim.x) >> 4;
    int npair  = (n_edge + 1) >> 1;

    int p = group;
    int2 c0a, c0b, c0c, c1a, c1b, c1c;
    if (p < npair) {
        const int2* e0 = (const int2*)edges + (long)(p * 2) * 3;
        c0a = __ldcs(e0); c0b = __ldcs(e0 + 1); c0c = __ldcs(e0 + 2);
        if (p * 2 + 1 < n_edge) {
            c1a = __ldcs(e0 + 3); c1b = __ldcs(e0 + 4); c1c = __ldcs(e0 + 5);
        } else { c1a = c0a; c1b = c0b; c1c = c0c; }
    }

    while (p < npair) {
        int2 i0a = c0a, i0b = c0b, i0c = c0c;
        int2 i1a = c1a, i1b = c1b, i1c = c1c;
        bool has1 = (p * 2 + 1) < n_edge;

        int pn = p + stride;
        if (pn < npair) {
            const int2* e0 = (const int2*)edges + (long)(pn * 2) * 3;
            c0a = __ldcs(e0); c0b = __ldcs(e0 + 1); c0c = __ldcs(e0 + 2);
            if (pn * 2 + 1 < n_edge) {
                c1a = __ldcs(e0 + 3); c1b = __ldcs(e0 + 4); c1c = __ldcs(e0 + 5);
            }
        }

        EdgeVals v0, v1;
        edge_load(hidden, rela, wa, l, i0a.x, i0b.x, i0c.x, i0c.y, v0);
        if (has1) edge_load(hidden, rela, wa, l, i1a.x, i1b.x, i1c.x, i1c.y, v1);
        else v1.s = 0;

        float a = v0.s, b = v1.s;
#pragma unroll
        for (int o = 8; o; o >>= 1) {
            a += __shfl_xor_sync(0xffffffffu, a, o);
            b += __shfl_xor_sync(0xffffffffu, b, o);
        }
        v0.s = a; v1.s = b;

        edge_finish(v0, out, l);
        if (has1) edge_finish(v1, out, l);

        p = pn;
    }
}

// ---------------------------------------------------------------------------
// final: out[n] = logmap0(relu(expmap0(Wh @ agg[n])))  (in-place)
// 4 rows per 64-thread group; fused Σacc² / Σrelu(acc)² single reduction.
// Exact (poly) math kept: ||agg||² can be O(1e3) where corrections ~1e-4.
// ---------------------------------------------------------------------------
__global__ __launch_bounds__(256) void final_kernel(
    const float* __restrict__ Wh, float* __restrict__ out, int n_node)
{
    __shared__ float Wst[DD][DD + 1];
    __shared__ __align__(16) float hT[4][DD * 4];
    __shared__ float red2[4][2][8];

    int t = threadIdx.x;
    for (int i = t; i < DD * DD; i += 256) Wst[i & 63][i >> 6] = Wh[i];

    int g = t >> 6, j = t & 63, half = (t >> 5) & 1, lane = t & 31;

    float pf[4];
    {
        int rbase = blockIdx.x * ROWS_PER_BLOCK + g * 4;
#pragma unroll
        for (int u = 0; u < 4; u++) {
            int row = rbase + u;
            pf[u] = (row < n_node) ? __ldg(&out[row * DD + j]) : 0.0f;
        }
    }

    for (int tile = 0; tile < TILES; tile++) {
        int base = blockIdx.x * ROWS_PER_BLOCK + tile * ROWS_PER_TILE;
        if (base >= n_node) break;

        if (tile > 0) __syncthreads();
        *(float4*)&hT[g][j * 4] = make_float4(pf[0], pf[1], pf[2], pf[3]);
        __syncthreads();

        int nbase = base + ROWS_PER_TILE;
        if (tile + 1 < TILES && nbase < n_node) {
            int rbase = nbase + g * 4;
#pragma unroll
            for (int u = 0; u < 4; u++) {
                int row = rbase + u;
                pf[u] = (row < n_node) ? __ldg(&out[row * DD + j]) : 0.0f;
            }
        }

        unsigned long long a01 = 0ull, a23 = 0ull;
#pragma unroll
        for (int k = 0; k < DD; k++) {
            float w = Wst[k][j];
            unsigned long long ww = pack2(w, w);
            ulonglong2 hh = *(const ulonglong2*)&hT[g][k * 4];
            a01 = fma2(ww, hh.x, a01);
            a23 = fma2(ww, hh.y, a23);
        }
        float acc[4];
        unpack2(a01, acc[0], acc[1]);
        unpack2(a23, acc[2], acc[3]);

        // fused reduction: Σacc² and Σmax(acc,0)² per row
        float sa[4], sp[4];
#pragma unroll
        for (int u = 0; u < 4; u++) {
            float ap = fmaxf(acc[u], 0.0f);
            sa[u] = acc[u] * acc[u];
            sp[u] = ap * ap;
        }
#pragma unroll
        for (int o = 16; o; o >>= 1) {
#pragma unroll
            for (int u = 0; u < 4; u++) {
                sa[u] += __shfl_xor_sync(0xffffffffu, sa[u], o);
                sp[u] += __shfl_xor_sync(0xffffffffu, sp[u], o);
            }
        }
        if (lane == 0) {
#pragma unroll
            for (int u = 0; u < 4; u++) {
                red2[g][half][u]     = sa[u];
                red2[g][half][4 + u] = sp[u];
            }
        }
        __syncthreads();

        int rbase = base + g * 4;
#pragma unroll
        for (int u = 0; u < 4; u++) {
            int row = rbase + u;
            if (row >= n_node) continue;
            float nv2 = red2[g][0][u]     + red2[g][1][u];
            float sp2 = red2[g][0][4 + u] + red2[g][1][4 + u];
            float fac = tanh_ratio(CC * nv2);
            float rn2 = fac * fac * nv2;
            float ps  = 1.0f;
            if (rn2 > MN2) ps = MAXNORM * rsqrtf(rn2);
            float fp  = fac * ps;
            float na2 = fp * fp * sp2;               // ||relu(expmap0)||^2
            float gg  = artanh_ratio(CC * na2);
            out[row * DD + j] = fp * fmaxf(acc[u], 0.0f) * gg;
        }
    }
}

// ---------------------------------------------------------------------------
extern "C" void kernel_launch(void* const* d_in, const int* in_sizes, int n_in,
                              void* d_out, int out_size)
{
    const float* hidden = (const float*)d_in[0];
    const int*   q_rel  = (const int*)  d_in[1];
    const int*   edges  = (const int*)  d_in[2];
    const float* rela   = (const float*)d_in[3];
    const float* Ws     = (const float*)d_in[4];
    const float* Wr     = (const float*)d_in[5];
    const float* Wqr    = (const float*)d_in[6];
    const float* Wqr_b  = (const float*)d_in[7];
    const float* Wattn  = (const float*)d_in[8];
    const float* Wh     = (const float*)d_in[9];
    float* out = (float*)d_out;

    int n_node  = in_sizes[0] / DD;
    int Bn      = in_sizes[1];
    int n_edge  = in_sizes[2] / 6;
    int n_vocab = in_sizes[3] / DD;

    // zero accumulator (graph-capturable memset node)
    cudaMemsetAsync(out, 0, (size_t)out_size * sizeof(float));

    int nb0 = (n_node  + ROWS_PER_BLOCK - 1) / ROWS_PER_BLOCK;
    int nb1 = (n_vocab + ROWS_PER_BLOCK - 1) / ROWS_PER_BLOCK;
    int nb2 = (Bn      + ROWS_PER_BLOCK - 1) / ROWS_PER_BLOCK;

    prep_all<<<nb0 + nb1 + nb2, 256>>>(Ws, Wr, Wqr, hidden, rela, q_rel, Wqr_b,
                                       n_node, n_vocab, Bn, nb0, nb1);

    edge_kernel<<<2368, 256>>>(edges, Wattn, hidden, rela, out, n_edge);

    final_kernel<<<(n_node + ROWS_PER_BLOCK - 1) / ROWS_PER_BLOCK, 256>>>(Wh, out, n_node);
}

// round 10
// speedup vs baseline: 1.5122x; 1.2400x over previous
#include <cuda_runtime.h>
#include <cuda_bf16.h>
#include <math.h>

// ---------------------------------------------------------------------------
// GNNModel: hyperbolic GNN message passing (c = 1e-6)
//
// Edge path: with c=1e-6 and data scale 0.1, expmap0/mobius/logmap0 are
// identity to O(1e-6) relative (tolerance 1e-3):
//   message = sigmoid(attn) * (hidden[sub] + rela_embed[rel])
// Final per-node transform keeps exact (polynomial) math (||agg||^2 ~ O(1e3)).
// Prep = pure GEMV -> bf16 attention tables == a bf16 GEMM -> tensor cores.
// ---------------------------------------------------------------------------

#define MAX_NODE 100000
#define MAX_VOCAB 512
#define MAX_B 256
#define DD 64
#define TILES 4
#define ROWS_PER_TILE 16
#define ROWS_PER_BLOCK (TILES * ROWS_PER_TILE)   // 64

// attention tables in bf16 (only feed sigmoid(relu(.)@Wattn) — error << 1e-3)
__device__ __align__(16) __nv_bfloat16 g_hs_projh [MAX_NODE * DD];
__device__ __align__(16) __nv_bfloat16 g_rel_projh[MAX_VOCAB * DD];
__device__ __align__(16) __nv_bfloat16 g_qr_projh [MAX_B * DD];

#define SC 1.0e-3f                    // sqrt(c), c = 1e-6
#define CC 1.0e-6f
#define MAXNORM (0.996f / SC)
#define MN2 (MAXNORM * MAXNORM)

// ---- packed f32x2 helpers ----
__device__ __forceinline__ unsigned long long pack2(float a, float b) {
    unsigned long long r;
    asm("mov.b64 %0, {%1, %2};" : "=l"(r)
        : "r"(__float_as_uint(a)), "r"(__float_as_uint(b)));
    return r;
}
__device__ __forceinline__ void unpack2(unsigned long long v, float& a, float& b) {
    unsigned lo, hi;
    asm("mov.b64 {%0, %1}, %2;" : "=r"(lo), "=r"(hi) : "l"(v));
    a = __uint_as_float(lo); b = __uint_as_float(hi);
}
__device__ __forceinline__ unsigned long long fma2(
    unsigned long long a, unsigned long long b, unsigned long long c) {
    unsigned long long d;
    asm("fma.rn.f32x2 %0, %1, %2, %3;" : "=l"(d) : "l"(a), "l"(b), "l"(c));
    return d;
}
// bf16 pair (packed in u32) -> two f32, pure ALU
__device__ __forceinline__ float bflo(unsigned u) { return __uint_as_float(u << 16); }
__device__ __forceinline__ float bfhi(unsigned u) { return __uint_as_float(u & 0xffff0000u); }

// artanh(z)/z as poly in z^2 (valid z^2 < 0.09, guarded fallback above)
__device__ __forceinline__ float artanh_ratio(float z2) {
    float f = fmaf(z2, fmaf(z2, fmaf(z2, fmaf(z2, 1.0f/9.0f, 1.0f/7.0f),
                                     0.2f), 1.0f/3.0f), 1.0f);
    if (z2 > 0.09f) {
        float z = sqrtf(z2);
        float zc = fminf(z, 1.0f - 1e-5f);
        f = 0.5f * (log1pf(zc) - log1pf(-zc)) / z;
    }
    return f;
}
// tanh(z)/z as poly in z^2 (valid z^2 < 0.09, guarded)
__device__ __forceinline__ float tanh_ratio(float z2) {
    float f = fmaf(z2, fmaf(z2, fmaf(z2, -17.0f/315.0f, 2.0f/15.0f),
                            -1.0f/3.0f), 1.0f);
    if (z2 > 0.09f) {
        float z = sqrtf(z2);
        f = tanhf(fminf(z, 15.0f)) / z;
    }
    return f;
}

__device__ __forceinline__ unsigned cvta_sh(const void* p) {
    return (unsigned)__cvta_generic_to_shared(p);
}

// ---------------------------------------------------------------------------
// GEMM prep (tensor cores): proj[row, :] = W @ src[row] (+bias, mode 2).
// One launch; blockIdx routes mode. 64 rows/block, 128 threads (4 warps).
// A,B staged f32->bf16 in shared (stride 72 bf16 = 144B: 16B-aligned rows,
// 9-group rotation => conflict-free ldmatrix). Warp w: rows w*16..w*16+15,
// mma.sync m16n8k16 row.col f32.bf16.bf16.f32, 8 n-tiles x 4 k-tiles.
// ---------------------------------------------------------------------------
#define ASTRIDE 72

__global__ __launch_bounds__(128) void prep_gemm(
    const float* __restrict__ Ws, const float* __restrict__ Wr,
    const float* __restrict__ Wqr, const float* __restrict__ hidden,
    const float* __restrict__ rela, const int* __restrict__ q_rel,
    const float* __restrict__ Wqr_b,
    int n_node, int n_vocab, int nB, int nb0, int nb1)
{
    __shared__ __align__(16) __nv_bfloat16 Asm[64 * ASTRIDE];
    __shared__ __align__(16) __nv_bfloat16 Bsm[64 * ASTRIDE];

    int mode, bidx, n_rows;
    const float* W; const float* src;
    if ((int)blockIdx.x < nb0) {
        mode = 0; bidx = blockIdx.x; W = Ws; src = hidden; n_rows = n_node;
    } else if ((int)blockIdx.x < nb0 + nb1) {
        mode = 1; bidx = blockIdx.x - nb0; W = Wr; src = rela; n_rows = n_vocab;
    } else {
        mode = 2; bidx = blockIdx.x - nb0 - nb1; W = Wqr; src = rela; n_rows = nB;
    }
    int base = bidx * ROWS_PER_BLOCK;

    int t = threadIdx.x;
    int w = t >> 5, lane = t & 31;
    int l16 = lane & 15, hi16 = lane >> 4;   // 2 rows per warp-iteration

    // ---- stage W (f32 -> bf16), warp w rows w*16..+15, coalesced ----
    {
        int k4 = l16 * 4;
#pragma unroll
        for (int i = 0; i < 8; i++) {
            int row = w * 16 + i * 2 + hi16;
            float4 v = __ldg((const float4*)&W[row * DD + k4]);
            __nv_bfloat162 lo = __floats2bfloat162_rn(v.x, v.y);
            __nv_bfloat162 hi = __floats2bfloat162_rn(v.z, v.w);
            *(__nv_bfloat162*)&Bsm[row * ASTRIDE + k4]     = lo;
            *(__nv_bfloat162*)&Bsm[row * ASTRIDE + k4 + 2] = hi;
        }
    }
    // ---- stage A rows (gather for mode 2), zero-fill OOB ----
    {
        int k4 = l16 * 4;
#pragma unroll
        for (int i = 0; i < 8; i++) {
            int rloc = w * 16 + i * 2 + hi16;
            int row = base + rloc;
            float4 v = make_float4(0.f, 0.f, 0.f, 0.f);
            if (row < n_rows) {
                int sr = (mode == 2) ? __ldg(&q_rel[row]) : row;
                v = __ldg((const float4*)&src[sr * DD + k4]);
            }
            __nv_bfloat162 lo = __floats2bfloat162_rn(v.x, v.y);
            __nv_bfloat162 hi = __floats2bfloat162_rn(v.z, v.w);
            *(__nv_bfloat162*)&Asm[rloc * ASTRIDE + k4]     = lo;
            *(__nv_bfloat162*)&Asm[rloc * ASTRIDE + k4 + 2] = hi;
        }
    }
    __syncthreads();

    // ---- A fragments: 4 k-tiles, ldmatrix.x4 each ----
    int m0 = w * 16;
    unsigned a[4][4];
#pragma unroll
    for (int kt = 0; kt < 4; kt++) {
        int arow = m0 + (lane & 15);
        int acol = kt * 16 + (lane >> 4) * 8;
        unsigned addr = cvta_sh(&Asm[arow * ASTRIDE + acol]);
        asm volatile("ldmatrix.sync.aligned.m8n8.x4.shared.b16 {%0,%1,%2,%3}, [%4];"
                     : "=r"(a[kt][0]), "=r"(a[kt][1]), "=r"(a[kt][2]), "=r"(a[kt][3])
                     : "r"(addr));
    }

    __nv_bfloat16* projh = (mode == 0) ? g_hs_projh :
                           (mode == 1) ? g_rel_projh : g_qr_projh;

    int gid = lane >> 2, qid = lane & 3;

#pragma unroll
    for (int nt = 0; nt < 8; nt++) {
        float d0 = 0.f, d1 = 0.f, d2 = 0.f, d3 = 0.f;
#pragma unroll
        for (int kt = 0; kt < 4; kt++) {
            int jrow = nt * 8 + (lane & 7);
            int jcol = kt * 16 + ((lane >> 3) & 1) * 8;
            unsigned baddr = cvta_sh(&Bsm[jrow * ASTRIDE + jcol]);
            unsigned b0, b1;
            asm volatile("ldmatrix.sync.aligned.m8n8.x2.shared.b16 {%0,%1}, [%2];"
                         : "=r"(b0), "=r"(b1) : "r"(baddr));
            asm volatile(
                "mma.sync.aligned.m16n8k16.row.col.f32.bf16.bf16.f32 "
                "{%0,%1,%2,%3}, {%4,%5,%6,%7}, {%8,%9}, {%0,%1,%2,%3};"
                : "+f"(d0), "+f"(d1), "+f"(d2), "+f"(d3)
                : "r"(a[kt][0]), "r"(a[kt][1]), "r"(a[kt][2]), "r"(a[kt][3]),
                  "r"(b0), "r"(b1));
        }

        int col = nt * 8 + qid * 2;
        if (mode == 2) {
            float2 bb = __ldg((const float2*)&Wqr_b[col]);
            d0 += bb.x; d1 += bb.y; d2 += bb.x; d3 += bb.y;
        }
        int row0 = base + m0 + gid;
        int row1 = row0 + 8;
        if (row0 < n_rows) {
            __nv_bfloat162 p = __floats2bfloat162_rn(d0, d1);
            *(__nv_bfloat162*)&projh[row0 * DD + col] = p;
        }
        if (row1 < n_rows) {
            __nv_bfloat162 p = __floats2bfloat162_rn(d2, d3);
            *(__nv_bfloat162*)&projh[row1 * DD + col] = p;
        }
    }
}

// ---------------------------------------------------------------------------
// edge kernel: 16 lanes per group, 2 consecutive edges per group per iter,
// edge indices software-pipelined; packed bf16x2 attention math.
// message = sigmoid(attn) * (hidden[sub] + rela_embed[rel])
// ---------------------------------------------------------------------------
struct EdgeVals {
    int obj;
    float s;
    float4 hx, y;
};

__device__ __forceinline__ void edge_load(
    const float* __restrict__ hidden, const float* __restrict__ rela,
    float4 wa, int l, int r_idx, int rel, int sub, int obj, EdgeVals& v)
{
    v.obj = obj;

    uint2 pb = __ldg((const uint2*)g_hs_projh  + sub   * 16 + l);
    uint2 rb = __ldg((const uint2*)g_rel_projh + rel   * 16 + l);
    uint2 qb = __ldg((const uint2*)g_qr_projh  + r_idx * 16 + l);

    __nv_bfloat162 z2b; *(unsigned*)&z2b = 0u;
    __nv_bfloat162 t0 = __hmax2(__hadd2(__hadd2(*(__nv_bfloat162*)&pb.x,
                                                *(__nv_bfloat162*)&rb.x),
                                        *(__nv_bfloat162*)&qb.x), z2b);
    __nv_bfloat162 t1 = __hmax2(__hadd2(__hadd2(*(__nv_bfloat162*)&pb.y,
                                                *(__nv_bfloat162*)&rb.y),
                                        *(__nv_bfloat162*)&qb.y), z2b);
    unsigned u0 = *(unsigned*)&t0, u1 = *(unsigned*)&t1;
    float s = bflo(u0) * wa.x;
    s = fmaf(bfhi(u0), wa.y, s);
    s = fmaf(bflo(u1), wa.z, s);
    s = fmaf(bfhi(u1), wa.w, s);
    v.s = s;

    v.hx = __ldg((const float4*)hidden + sub * 16 + l);
    v.y  = __ldg((const float4*)rela   + rel * 16 + l);
}

__device__ __forceinline__ void edge_finish(
    const EdgeVals& v, float* __restrict__ out, int l)
{
    float alpha = __fdividef(1.0f, 1.0f + __expf(-v.s));

    float g0 = alpha * (v.hx.x + v.y.x);
    float g1 = alpha * (v.hx.y + v.y.y);
    float g2 = alpha * (v.hx.z + v.y.z);
    float g3 = alpha * (v.hx.w + v.y.w);

    float* dst = out + (long)v.obj * DD + l * 4;
    asm volatile("red.global.add.v4.f32 [%0], {%1,%2,%3,%4};"
                 :: "l"(dst), "f"(g0), "f"(g1), "f"(g2), "f"(g3) : "memory");
}

__global__ __launch_bounds__(256) void edge_kernel(
    const int* __restrict__ edges, const float* __restrict__ Wattn,
    const float* __restrict__ hidden, const float* __restrict__ rela,
    float* __restrict__ out, int n_edge)
{
    int l = threadIdx.x & 15;
    float4 wa = __ldg((const float4*)Wattn + l);
    int group  = (blockIdx.x * blockDim.x + threadIdx.x) >> 4;
    int stride = (gridDim.x * blockDim.x) >> 4;
    int npair  = (n_edge + 1) >> 1;

    int p = group;
    int2 c0a, c0b, c0c, c1a, c1b, c1c;
    if (p < npair) {
        const int2* e0 = (const int2*)edges + (long)(p * 2) * 3;
        c0a = __ldcs(e0); c0b = __ldcs(e0 + 1); c0c = __ldcs(e0 + 2);
        if (p * 2 + 1 < n_edge) {
            c1a = __ldcs(e0 + 3); c1b = __ldcs(e0 + 4); c1c = __ldcs(e0 + 5);
        } else { c1a = c0a; c1b = c0b; c1c = c0c; }
    }

    while (p < npair) {
        int2 i0a = c0a, i0b = c0b, i0c = c0c;
        int2 i1a = c1a, i1b = c1b, i1c = c1c;
        bool has1 = (p * 2 + 1) < n_edge;

        int pn = p + stride;
        if (pn < npair) {
            const int2* e0 = (const int2*)edges + (long)(pn * 2) * 3;
            c0a = __ldcs(e0); c0b = __ldcs(e0 + 1); c0c = __ldcs(e0 + 2);
            if (pn * 2 + 1 < n_edge) {
                c1a = __ldcs(e0 + 3); c1b = __ldcs(e0 + 4); c1c = __ldcs(e0 + 5);
            }
        }

        EdgeVals v0, v1;
        edge_load(hidden, rela, wa, l, i0a.x, i0b.x, i0c.x, i0c.y, v0);
        if (has1) edge_load(hidden, rela, wa, l, i1a.x, i1b.x, i1c.x, i1c.y, v1);
        else v1.s = 0;

        float a = v0.s, b = v1.s;
#pragma unroll
        for (int o = 8; o; o >>= 1) {
            a += __shfl_xor_sync(0xffffffffu, a, o);
            b += __shfl_xor_sync(0xffffffffu, b, o);
        }
        v0.s = a; v1.s = b;

        edge_finish(v0, out, l);
        if (has1) edge_finish(v1, out, l);

        p = pn;
    }
}

// ---------------------------------------------------------------------------
// final: out[n] = logmap0(relu(expmap0(Wh @ agg[n])))  (in-place)
// 4 rows per 64-thread group; fused Σacc² / Σrelu(acc)² single reduction.
// Exact (poly) math kept: ||agg||² can be O(1e3) where corrections ~1e-4.
// ---------------------------------------------------------------------------
__global__ __launch_bounds__(256) void final_kernel(
    const float* __restrict__ Wh, float* __restrict__ out, int n_node)
{
    __shared__ float Wst[DD][DD + 1];
    __shared__ __align__(16) float hT[4][DD * 4];
    __shared__ float red2[4][2][8];

    int t = threadIdx.x;
    for (int i = t; i < DD * DD; i += 256) Wst[i & 63][i >> 6] = Wh[i];

    int g = t >> 6, j = t & 63, half = (t >> 5) & 1, lane = t & 31;

    float pf[4];
    {
        int rbase = blockIdx.x * ROWS_PER_BLOCK + g * 4;
#pragma unroll
        for (int u = 0; u < 4; u++) {
            int row = rbase + u;
            pf[u] = (row < n_node) ? __ldg(&out[row * DD + j]) : 0.0f;
        }
    }

    for (int tile = 0; tile < TILES; tile++) {
        int base = blockIdx.x * ROWS_PER_BLOCK + tile * ROWS_PER_TILE;
        if (base >= n_node) break;

        if (tile > 0) __syncthreads();
        *(float4*)&hT[g][j * 4] = make_float4(pf[0], pf[1], pf[2], pf[3]);
        __syncthreads();

        int nbase = base + ROWS_PER_TILE;
        if (tile + 1 < TILES && nbase < n_node) {
            int rbase = nbase + g * 4;
#pragma unroll
            for (int u = 0; u < 4; u++) {
                int row = rbase + u;
                pf[u] = (row < n_node) ? __ldg(&out[row * DD + j]) : 0.0f;
            }
        }

        unsigned long long a01 = 0ull, a23 = 0ull;
#pragma unroll
        for (int k = 0; k < DD; k++) {
            float w = Wst[k][j];
            unsigned long long ww = pack2(w, w);
            ulonglong2 hh = *(const ulonglong2*)&hT[g][k * 4];
            a01 = fma2(ww, hh.x, a01);
            a23 = fma2(ww, hh.y, a23);
        }
        float acc[4];
        unpack2(a01, acc[0], acc[1]);
        unpack2(a23, acc[2], acc[3]);

        // fused reduction: Σacc² and Σmax(acc,0)² per row
        float sa[4], sp[4];
#pragma unroll
        for (int u = 0; u < 4; u++) {
            float ap = fmaxf(acc[u], 0.0f);
            sa[u] = acc[u] * acc[u];
            sp[u] = ap * ap;
        }
#pragma unroll
        for (int o = 16; o; o >>= 1) {
#pragma unroll
            for (int u = 0; u < 4; u++) {
                sa[u] += __shfl_xor_sync(0xffffffffu, sa[u], o);
                sp[u] += __shfl_xor_sync(0xffffffffu, sp[u], o);
            }
        }
        if (lane == 0) {
#pragma unroll
            for (int u = 0; u < 4; u++) {
                red2[g][half][u]     = sa[u];
                red2[g][half][4 + u] = sp[u];
            }
        }
        __syncthreads();

        int rbase = base + g * 4;
#pragma unroll
        for (int u = 0; u < 4; u++) {
            int row = rbase + u;
            if (row >= n_node) continue;
            float nv2 = red2[g][0][u]     + red2[g][1][u];
            float sp2 = red2[g][0][4 + u] + red2[g][1][4 + u];
            float fac = tanh_ratio(CC * nv2);
            float rn2 = fac * fac * nv2;
            float ps  = 1.0f;
            if (rn2 > MN2) ps = MAXNORM * rsqrtf(rn2);
            float fp  = fac * ps;
            float na2 = fp * fp * sp2;               // ||relu(expmap0)||^2
            float gg  = artanh_ratio(CC * na2);
            out[row * DD + j] = fp * fmaxf(acc[u], 0.0f) * gg;
        }
    }
}

// ---------------------------------------------------------------------------
extern "C" void kernel_launch(void* const* d_in, const int* in_sizes, int n_in,
                              void* d_out, int out_size)
{
    const float* hidden = (const float*)d_in[0];
    const int*   q_rel  = (const int*)  d_in[1];
    const int*   edges  = (const int*)  d_in[2];
    const float* rela   = (const float*)d_in[3];
    const float* Ws     = (const float*)d_in[4];
    const float* Wr     = (const float*)d_in[5];
    const float* Wqr    = (const float*)d_in[6];
    const float* Wqr_b  = (const float*)d_in[7];
    const float* Wattn  = (const float*)d_in[8];
    const float* Wh     = (const float*)d_in[9];
    float* out = (float*)d_out;

    int n_node  = in_sizes[0] / DD;
    int Bn      = in_sizes[1];
    int n_edge  = in_sizes[2] / 6;
    int n_vocab = in_sizes[3] / DD;

    // zero accumulator (graph-capturable memset node)
    cudaMemsetAsync(out, 0, (size_t)out_size * sizeof(float));

    int nb0 = (n_node  + ROWS_PER_BLOCK - 1) / ROWS_PER_BLOCK;
    int nb1 = (n_vocab + ROWS_PER_BLOCK - 1) / ROWS_PER_BLOCK;
    int nb2 = (Bn      + ROWS_PER_BLOCK - 1) / ROWS_PER_BLOCK;

    prep_gemm<<<nb0 + nb1 + nb2, 128>>>(Ws, Wr, Wqr, hidden, rela, q_rel, Wqr_b,
                                        n_node, n_vocab, Bn, nb0, nb1);

    edge_kernel<<<2368, 256>>>(edges, Wattn, hidden, rela, out, n_edge);

    final_kernel<<<(n_node + ROWS_PER_BLOCK - 1) / ROWS_PER_BLOCK, 256>>>(Wh, out, n_node);
}

// round 11
// speedup vs baseline: 2.1836x; 1.4440x over previous
#include <cuda_runtime.h>
#include <cuda_bf16.h>
#include <math.h>

// ---------------------------------------------------------------------------
// GNNModel: hyperbolic GNN message passing (c = 1e-6)
//
// Edge path: with c=1e-6 and data scale 0.1, expmap0/mobius/logmap0 are
// identity to O(1e-6) relative (tolerance 1e-3):
//   message = sigmoid(attn) * (hidden[sub] + rela_embed[rel])
// Final per-node transform keeps exact math via split-bf16 tensor-core GEMM
// (A = A_hi + A_lo, W = W_hi + W_lo; 3 MMAs; dropped term ~2^-16).
// ---------------------------------------------------------------------------

#define MAX_NODE 100000
#define MAX_VOCAB 512
#define MAX_B 256
#define DD 64

// attention tables in bf16 (only feed sigmoid(relu(.)@Wattn) — error << 1e-3)
__device__ __align__(16) __nv_bfloat16 g_hs_projh [MAX_NODE * DD];
__device__ __align__(16) __nv_bfloat16 g_rel_projh[MAX_VOCAB * DD];
__device__ __align__(16) __nv_bfloat16 g_qr_projh [MAX_B * DD];

#define SC 1.0e-3f                    // sqrt(c), c = 1e-6
#define CC 1.0e-6f
#define MAXNORM (0.996f / SC)
#define MN2 (MAXNORM * MAXNORM)

// bf16 pair (packed in u32) -> two f32, pure ALU
__device__ __forceinline__ float bflo(unsigned u) { return __uint_as_float(u << 16); }
__device__ __forceinline__ float bfhi(unsigned u) { return __uint_as_float(u & 0xffff0000u); }

// artanh(z)/z as poly in z^2 (valid z^2 < 0.09, guarded fallback above)
__device__ __forceinline__ float artanh_ratio(float z2) {
    float f = fmaf(z2, fmaf(z2, fmaf(z2, fmaf(z2, 1.0f/9.0f, 1.0f/7.0f),
                                     0.2f), 1.0f/3.0f), 1.0f);
    if (z2 > 0.09f) {
        float z = sqrtf(z2);
        float zc = fminf(z, 1.0f - 1e-5f);
        f = 0.5f * (log1pf(zc) - log1pf(-zc)) / z;
    }
    return f;
}
// tanh(z)/z as poly in z^2 (valid z^2 < 0.09, guarded)
__device__ __forceinline__ float tanh_ratio(float z2) {
    float f = fmaf(z2, fmaf(z2, fmaf(z2, -17.0f/315.0f, 2.0f/15.0f),
                            -1.0f/3.0f), 1.0f);
    if (z2 > 0.09f) {
        float z = sqrtf(z2);
        f = tanhf(fminf(z, 15.0f)) / z;
    }
    return f;
}

__device__ __forceinline__ unsigned cvta_sh(const void* p) {
    return (unsigned)__cvta_generic_to_shared(p);
}

#define ASTRIDE 72

// ---------------------------------------------------------------------------
// GEMM prep (tensor cores): proj[row, :] = W @ src[row] (+bias, mode 2).
// One launch; blockIdx routes mode. 64 rows/block, 128 threads (4 warps).
// ---------------------------------------------------------------------------
__global__ __launch_bounds__(128) void prep_gemm(
    const float* __restrict__ Ws, const float* __restrict__ Wr,
    const float* __restrict__ Wqr, const float* __restrict__ hidden,
    const float* __restrict__ rela, const int* __restrict__ q_rel,
    const float* __restrict__ Wqr_b,
    int n_node, int n_vocab, int nB, int nb0, int nb1)
{
    __shared__ __align__(16) __nv_bfloat16 Asm[64 * ASTRIDE];
    __shared__ __align__(16) __nv_bfloat16 Bsm[64 * ASTRIDE];

    int mode, bidx, n_rows;
    const float* W; const float* src;
    if ((int)blockIdx.x < nb0) {
        mode = 0; bidx = blockIdx.x; W = Ws; src = hidden; n_rows = n_node;
    } else if ((int)blockIdx.x < nb0 + nb1) {
        mode = 1; bidx = blockIdx.x - nb0; W = Wr; src = rela; n_rows = n_vocab;
    } else {
        mode = 2; bidx = blockIdx.x - nb0 - nb1; W = Wqr; src = rela; n_rows = nB;
    }
    int base = bidx * 64;

    int t = threadIdx.x;
    int w = t >> 5, lane = t & 31;
    int l16 = lane & 15, hi16 = lane >> 4;

    {
        int k4 = l16 * 4;
#pragma unroll
        for (int i = 0; i < 8; i++) {
            int row = w * 16 + i * 2 + hi16;
            float4 v = __ldg((const float4*)&W[row * DD + k4]);
            *(__nv_bfloat162*)&Bsm[row * ASTRIDE + k4]     = __floats2bfloat162_rn(v.x, v.y);
            *(__nv_bfloat162*)&Bsm[row * ASTRIDE + k4 + 2] = __floats2bfloat162_rn(v.z, v.w);
        }
    }
    {
        int k4 = l16 * 4;
#pragma unroll
        for (int i = 0; i < 8; i++) {
            int rloc = w * 16 + i * 2 + hi16;
            int row = base + rloc;
            float4 v = make_float4(0.f, 0.f, 0.f, 0.f);
            if (row < n_rows) {
                int sr = (mode == 2) ? __ldg(&q_rel[row]) : row;
                v = __ldg((const float4*)&src[sr * DD + k4]);
            }
            *(__nv_bfloat162*)&Asm[rloc * ASTRIDE + k4]     = __floats2bfloat162_rn(v.x, v.y);
            *(__nv_bfloat162*)&Asm[rloc * ASTRIDE + k4 + 2] = __floats2bfloat162_rn(v.z, v.w);
        }
    }
    __syncthreads();

    int m0 = w * 16;
    unsigned a[4][4];
#pragma unroll
    for (int kt = 0; kt < 4; kt++) {
        int arow = m0 + (lane & 15);
        int acol = kt * 16 + (lane >> 4) * 8;
        unsigned addr = cvta_sh(&Asm[arow * ASTRIDE + acol]);
        asm volatile("ldmatrix.sync.aligned.m8n8.x4.shared.b16 {%0,%1,%2,%3}, [%4];"
                     : "=r"(a[kt][0]), "=r"(a[kt][1]), "=r"(a[kt][2]), "=r"(a[kt][3])
                     : "r"(addr));
    }

    __nv_bfloat16* projh = (mode == 0) ? g_hs_projh :
                           (mode == 1) ? g_rel_projh : g_qr_projh;

    int gid = lane >> 2, qid = lane & 3;

#pragma unroll
    for (int nt = 0; nt < 8; nt++) {
        float d0 = 0.f, d1 = 0.f, d2 = 0.f, d3 = 0.f;
#pragma unroll
        for (int kt = 0; kt < 4; kt++) {
            int jrow = nt * 8 + (lane & 7);
            int jcol = kt * 16 + ((lane >> 3) & 1) * 8;
            unsigned baddr = cvta_sh(&Bsm[jrow * ASTRIDE + jcol]);
            unsigned b0, b1;
            asm volatile("ldmatrix.sync.aligned.m8n8.x2.shared.b16 {%0,%1}, [%2];"
                         : "=r"(b0), "=r"(b1) : "r"(baddr));
            asm volatile(
                "mma.sync.aligned.m16n8k16.row.col.f32.bf16.bf16.f32 "
                "{%0,%1,%2,%3}, {%4,%5,%6,%7}, {%8,%9}, {%0,%1,%2,%3};"
                : "+f"(d0), "+f"(d1), "+f"(d2), "+f"(d3)
                : "r"(a[kt][0]), "r"(a[kt][1]), "r"(a[kt][2]), "r"(a[kt][3]),
                  "r"(b0), "r"(b1));
        }

        int col = nt * 8 + qid * 2;
        if (mode == 2) {
            float2 bb = __ldg((const float2*)&Wqr_b[col]);
            d0 += bb.x; d1 += bb.y; d2 += bb.x; d3 += bb.y;
        }
        int row0 = base + m0 + gid;
        int row1 = row0 + 8;
        if (row0 < n_rows)
            *(__nv_bfloat162*)&projh[row0 * DD + col] = __floats2bfloat162_rn(d0, d1);
        if (row1 < n_rows)
            *(__nv_bfloat162*)&projh[row1 * DD + col] = __floats2bfloat162_rn(d2, d3);
    }
}

// ---------------------------------------------------------------------------
// edge kernel: 16 lanes per group, 2 consecutive edges per group per iter,
// edge indices software-pipelined; packed bf16x2 attention math.
// message = sigmoid(attn) * (hidden[sub] + rela_embed[rel])
// ---------------------------------------------------------------------------
struct EdgeVals {
    int obj;
    float s;
    float4 hx, y;
};

__device__ __forceinline__ void edge_load(
    const float* __restrict__ hidden, const float* __restrict__ rela,
    float4 wa, int l, int r_idx, int rel, int sub, int obj, EdgeVals& v)
{
    v.obj = obj;

    uint2 pb = __ldg((const uint2*)g_hs_projh  + sub   * 16 + l);
    uint2 rb = __ldg((const uint2*)g_rel_projh + rel   * 16 + l);
    uint2 qb = __ldg((const uint2*)g_qr_projh  + r_idx * 16 + l);

    __nv_bfloat162 z2b; *(unsigned*)&z2b = 0u;
    __nv_bfloat162 t0 = __hmax2(__hadd2(__hadd2(*(__nv_bfloat162*)&pb.x,
                                                *(__nv_bfloat162*)&rb.x),
                                        *(__nv_bfloat162*)&qb.x), z2b);
    __nv_bfloat162 t1 = __hmax2(__hadd2(__hadd2(*(__nv_bfloat162*)&pb.y,
                                                *(__nv_bfloat162*)&rb.y),
                                        *(__nv_bfloat162*)&qb.y), z2b);
    unsigned u0 = *(unsigned*)&t0, u1 = *(unsigned*)&t1;
    float s = bflo(u0) * wa.x;
    s = fmaf(bfhi(u0), wa.y, s);
    s = fmaf(bflo(u1), wa.z, s);
    s = fmaf(bfhi(u1), wa.w, s);
    v.s = s;

    v.hx = __ldg((const float4*)hidden + sub * 16 + l);
    v.y  = __ldg((const float4*)rela   + rel * 16 + l);
}

__device__ __forceinline__ void edge_finish(
    const EdgeVals& v, float* __restrict__ out, int l)
{
    float alpha = __fdividef(1.0f, 1.0f + __expf(-v.s));

    float g0 = alpha * (v.hx.x + v.y.x);
    float g1 = alpha * (v.hx.y + v.y.y);
    float g2 = alpha * (v.hx.z + v.y.z);
    float g3 = alpha * (v.hx.w + v.y.w);

    float* dst = out + (long)v.obj * DD + l * 4;
    asm volatile("red.global.add.v4.f32 [%0], {%1,%2,%3,%4};"
                 :: "l"(dst), "f"(g0), "f"(g1), "f"(g2), "f"(g3) : "memory");
}

__global__ __launch_bounds__(256) void edge_kernel(
    const int* __restrict__ edges, const float* __restrict__ Wattn,
    const float* __restrict__ hidden, const float* __restrict__ rela,
    float* __restrict__ out, int n_edge)
{
    int l = threadIdx.x & 15;
    float4 wa = __ldg((const float4*)Wattn + l);
    int group  = (blockIdx.x * blockDim.x + threadIdx.x) >> 4;
    int stride = (gridDim.x * blockDim.x) >> 4;
    int npair  = (n_edge + 1) >> 1;

    int p = group;
    int2 c0a, c0b, c0c, c1a, c1b, c1c;
    if (p < npair) {
        const int2* e0 = (const int2*)edges + (long)(p * 2) * 3;
        c0a = __ldcs(e0); c0b = __ldcs(e0 + 1); c0c = __ldcs(e0 + 2);
        if (p * 2 + 1 < n_edge) {
            c1a = __ldcs(e0 + 3); c1b = __ldcs(e0 + 4); c1c = __ldcs(e0 + 5);
        } else { c1a = c0a; c1b = c0b; c1c = c0c; }
    }

    while (p < npair) {
        int2 i0a = c0a, i0b = c0b, i0c = c0c;
        int2 i1a = c1a, i1b = c1b, i1c = c1c;
        bool has1 = (p * 2 + 1) < n_edge;

        int pn = p + stride;
        if (pn < npair) {
            const int2* e0 = (const int2*)edges + (long)(pn * 2) * 3;
            c0a = __ldcs(e0); c0b = __ldcs(e0 + 1); c0c = __ldcs(e0 + 2);
            if (pn * 2 + 1 < n_edge) {
                c1a = __ldcs(e0 + 3); c1b = __ldcs(e0 + 4); c1c = __ldcs(e0 + 5);
            }
        }

        EdgeVals v0, v1;
        edge_load(hidden, rela, wa, l, i0a.x, i0b.x, i0c.x, i0c.y, v0);
        if (has1) edge_load(hidden, rela, wa, l, i1a.x, i1b.x, i1c.x, i1c.y, v1);
        else v1.s = 0;

        float a = v0.s, b = v1.s;
#pragma unroll
        for (int o = 8; o; o >>= 1) {
            a += __shfl_xor_sync(0xffffffffu, a, o);
            b += __shfl_xor_sync(0xffffffffu, b, o);
        }
        v0.s = a; v1.s = b;

        edge_finish(v0, out, l);
        if (has1) edge_finish(v1, out, l);

        p = pn;
    }
}

// ---------------------------------------------------------------------------
// final GEMM (tensor cores, split-bf16 for f32-accurate matvec):
// out[n] = logmap0(relu(expmap0(Wh @ agg[n])))  (in-place)
// acc = Whi@Ahi + Whi@Alo + Wlo@Ahi  (error ~2^-16).
// Fused epilogue: quad-reduced Σacc² / Σrelu(acc)², per-row poly transforms.
// ---------------------------------------------------------------------------
__global__ __launch_bounds__(128) void final_gemm(
    const float* __restrict__ Wh, float* __restrict__ out, int n_node)
{
    __shared__ __align__(16) __nv_bfloat16 Ahi[64 * ASTRIDE];
    __shared__ __align__(16) __nv_bfloat16 Alo[64 * ASTRIDE];
    __shared__ __align__(16) __nv_bfloat16 Bhi[64 * ASTRIDE];
    __shared__ __align__(16) __nv_bfloat16 Blo[64 * ASTRIDE];

    int base = blockIdx.x * 64;
    int t = threadIdx.x;
    int w = t >> 5, lane = t & 31;
    int l16 = lane & 15, hi16 = lane >> 4;

    // ---- stage Wh (hi/lo split) ----
    {
        int k4 = l16 * 4;
#pragma unroll
        for (int i = 0; i < 8; i++) {
            int row = w * 16 + i * 2 + hi16;
            float4 v = __ldg((const float4*)&Wh[row * DD + k4]);
            __nv_bfloat16 hx = __float2bfloat16_rn(v.x), hy = __float2bfloat16_rn(v.y);
            __nv_bfloat16 hz = __float2bfloat16_rn(v.z), hw = __float2bfloat16_rn(v.w);
            *(__nv_bfloat162*)&Bhi[row * ASTRIDE + k4]     = __nv_bfloat162(hx, hy);
            *(__nv_bfloat162*)&Bhi[row * ASTRIDE + k4 + 2] = __nv_bfloat162(hz, hw);
            *(__nv_bfloat162*)&Blo[row * ASTRIDE + k4] =
                __floats2bfloat162_rn(v.x - __bfloat162float(hx), v.y - __bfloat162float(hy));
            *(__nv_bfloat162*)&Blo[row * ASTRIDE + k4 + 2] =
                __floats2bfloat162_rn(v.z - __bfloat162float(hz), v.w - __bfloat162float(hw));
        }
    }
    // ---- stage A = agg rows (hi/lo split), zero-fill OOB ----
    {
        int k4 = l16 * 4;
#pragma unroll
        for (int i = 0; i < 8; i++) {
            int rloc = w * 16 + i * 2 + hi16;
            int row = base + rloc;
            float4 v = make_float4(0.f, 0.f, 0.f, 0.f);
            if (row < n_node) v = __ldg((const float4*)&out[row * DD + k4]);
            __nv_bfloat16 hx = __float2bfloat16_rn(v.x), hy = __float2bfloat16_rn(v.y);
            __nv_bfloat16 hz = __float2bfloat16_rn(v.z), hw = __float2bfloat16_rn(v.w);
            *(__nv_bfloat162*)&Ahi[rloc * ASTRIDE + k4]     = __nv_bfloat162(hx, hy);
            *(__nv_bfloat162*)&Ahi[rloc * ASTRIDE + k4 + 2] = __nv_bfloat162(hz, hw);
            *(__nv_bfloat162*)&Alo[rloc * ASTRIDE + k4] =
                __floats2bfloat162_rn(v.x - __bfloat162float(hx), v.y - __bfloat162float(hy));
            *(__nv_bfloat162*)&Alo[rloc * ASTRIDE + k4 + 2] =
                __floats2bfloat162_rn(v.z - __bfloat162float(hz), v.w - __bfloat162float(hw));
        }
    }
    __syncthreads();

    int m0 = w * 16;
    unsigned ahi[4][4], alo[4][4];
#pragma unroll
    for (int kt = 0; kt < 4; kt++) {
        int arow = m0 + (lane & 15);
        int acol = kt * 16 + (lane >> 4) * 8;
        unsigned addr = cvta_sh(&Ahi[arow * ASTRIDE + acol]);
        asm volatile("ldmatrix.sync.aligned.m8n8.x4.shared.b16 {%0,%1,%2,%3}, [%4];"
                     : "=r"(ahi[kt][0]), "=r"(ahi[kt][1]), "=r"(ahi[kt][2]), "=r"(ahi[kt][3])
                     : "r"(addr));
        unsigned addr2 = cvta_sh(&Alo[arow * ASTRIDE + acol]);
        asm volatile("ldmatrix.sync.aligned.m8n8.x4.shared.b16 {%0,%1,%2,%3}, [%4];"
                     : "=r"(alo[kt][0]), "=r"(alo[kt][1]), "=r"(alo[kt][2]), "=r"(alo[kt][3])
                     : "r"(addr2));
    }

    int gid = lane >> 2, qid = lane & 3;
    float acc0[16], acc1[16];   // row0 = base+m0+gid, row1 = row0+8; cols nt*8+qid*2{,+1}

#pragma unroll
    for (int nt = 0; nt < 8; nt++) {
        float d0 = 0.f, d1 = 0.f, d2 = 0.f, d3 = 0.f;
#pragma unroll
        for (int kt = 0; kt < 4; kt++) {
            int jrow = nt * 8 + (lane & 7);
            int jcol = kt * 16 + ((lane >> 3) & 1) * 8;
            unsigned bh0, bh1, bl0, bl1;
            unsigned baddr = cvta_sh(&Bhi[jrow * ASTRIDE + jcol]);
            asm volatile("ldmatrix.sync.aligned.m8n8.x2.shared.b16 {%0,%1}, [%2];"
                         : "=r"(bh0), "=r"(bh1) : "r"(baddr));
            unsigned baddr2 = cvta_sh(&Blo[jrow * ASTRIDE + jcol]);
            asm volatile("ldmatrix.sync.aligned.m8n8.x2.shared.b16 {%0,%1}, [%2];"
                         : "=r"(bl0), "=r"(bl1) : "r"(baddr2));
            asm volatile(
                "mma.sync.aligned.m16n8k16.row.col.f32.bf16.bf16.f32 "
                "{%0,%1,%2,%3}, {%4,%5,%6,%7}, {%8,%9}, {%0,%1,%2,%3};"
                : "+f"(d0), "+f"(d1), "+f"(d2), "+f"(d3)
                : "r"(ahi[kt][0]), "r"(ahi[kt][1]), "r"(ahi[kt][2]), "r"(ahi[kt][3]),
                  "r"(bh0), "r"(bh1));
            asm volatile(
                "mma.sync.aligned.m16n8k16.row.col.f32.bf16.bf16.f32 "
                "{%0,%1,%2,%3}, {%4,%5,%6,%7}, {%8,%9}, {%0,%1,%2,%3};"
                : "+f"(d0), "+f"(d1), "+f"(d2), "+f"(d3)
                : "r"(ahi[kt][0]), "r"(ahi[kt][1]), "r"(ahi[kt][2]), "r"(ahi[kt][3]),
                  "r"(bl0), "r"(bl1));
            asm volatile(
                "mma.sync.aligned.m16n8k16.row.col.f32.bf16.bf16.f32 "
                "{%0,%1,%2,%3}, {%4,%5,%6,%7}, {%8,%9}, {%0,%1,%2,%3};"
                : "+f"(d0), "+f"(d1), "+f"(d2), "+f"(d3)
                : "r"(alo[kt][0]), "r"(alo[kt][1]), "r"(alo[kt][2]), "r"(alo[kt][3]),
                  "r"(bh0), "r"(bh1));
        }
        acc0[nt * 2] = d0; acc0[nt * 2 + 1] = d1;
        acc1[nt * 2] = d2; acc1[nt * 2 + 1] = d3;
    }

    // fused per-row reductions: quad lanes (same gid) own the same 2 rows
    float sa0 = 0.f, sp0 = 0.f, sa1 = 0.f, sp1 = 0.f;
#pragma unroll
    for (int i = 0; i < 16; i++) {
        float a0 = acc0[i], a1 = acc1[i];
        float p0 = fmaxf(a0, 0.f), p1 = fmaxf(a1, 0.f);
        sa0 = fmaf(a0, a0, sa0); sp0 = fmaf(p0, p0, sp0);
        sa1 = fmaf(a1, a1, sa1); sp1 = fmaf(p1, p1, sp1);
    }
#pragma unroll
    for (int o = 1; o <= 2; o <<= 1) {
        sa0 += __shfl_xor_sync(0xffffffffu, sa0, o);
        sp0 += __shfl_xor_sync(0xffffffffu, sp0, o);
        sa1 += __shfl_xor_sync(0xffffffffu, sa1, o);
        sp1 += __shfl_xor_sync(0xffffffffu, sp1, o);
    }

    // per-row transforms
    float fac0 = tanh_ratio(CC * sa0);
    float rn20 = fac0 * fac0 * sa0;
    float ps0  = (rn20 > MN2) ? MAXNORM * rsqrtf(rn20) : 1.0f;
    float fp0  = fac0 * ps0;
    float gg0  = artanh_ratio(CC * (fp0 * fp0 * sp0));
    float m0s  = fp0 * gg0;

    float fac1 = tanh_ratio(CC * sa1);
    float rn21 = fac1 * fac1 * sa1;
    float ps1  = (rn21 > MN2) ? MAXNORM * rsqrtf(rn21) : 1.0f;
    float fp1  = fac1 * ps1;
    float gg1  = artanh_ratio(CC * (fp1 * fp1 * sp1));
    float m1s  = fp1 * gg1;

    int row0 = base + m0 + gid;
    int row1 = row0 + 8;
#pragma unroll
    for (int nt = 0; nt < 8; nt++) {
        int col = nt * 8 + qid * 2;
        if (row0 < n_node) {
            float2 v = make_float2(m0s * fmaxf(acc0[nt * 2], 0.f),
                                   m0s * fmaxf(acc0[nt * 2 + 1], 0.f));
            *(float2*)&out[row0 * DD + col] = v;
        }
        if (row1 < n_node) {
            float2 v = make_float2(m1s * fmaxf(acc1[nt * 2], 0.f),
                                   m1s * fmaxf(acc1[nt * 2 + 1], 0.f));
            *(float2*)&out[row1 * DD + col] = v;
        }
    }
}

// ---------------------------------------------------------------------------
extern "C" void kernel_launch(void* const* d_in, const int* in_sizes, int n_in,
                              void* d_out, int out_size)
{
    const float* hidden = (const float*)d_in[0];
    const int*   q_rel  = (const int*)  d_in[1];
    const int*   edges  = (const int*)  d_in[2];
    const float* rela   = (const float*)d_in[3];
    const float* Ws     = (const float*)d_in[4];
    const float* Wr     = (const float*)d_in[5];
    const float* Wqr    = (const float*)d_in[6];
    const float* Wqr_b  = (const float*)d_in[7];
    const float* Wattn  = (const float*)d_in[8];
    const float* Wh     = (const float*)d_in[9];
    float* out = (float*)d_out;

    int n_node  = in_sizes[0] / DD;
    int Bn      = in_sizes[1];
    int n_edge  = in_sizes[2] / 6;
    int n_vocab = in_sizes[3] / DD;

    // zero accumulator (graph-capturable memset node)
    cudaMemsetAsync(out, 0, (size_t)out_size * sizeof(float));

    int nb0 = (n_node  + 63) / 64;
    int nb1 = (n_vocab + 63) / 64;
    int nb2 = (Bn      + 63) / 64;

    prep_gemm<<<nb0 + nb1 + nb2, 128>>>(Ws, Wr, Wqr, hidden, rela, q_rel, Wqr_b,
                                        n_node, n_vocab, Bn, nb0, nb1);

    edge_kernel<<<2368, 256>>>(edges, Wattn, hidden, rela, out, n_edge);

    final_gemm<<<(n_node + 63) / 64, 128>>>(Wh, out, n_node);
}